// round 15
// baseline (speedup 1.0000x reference)
#include <cuda_runtime.h>
#include <cuda_bf16.h>
#include <math.h>
#include <stdint.h>

#define QLEN 1024
#define MLEN 1024
#define KLEN 2048
#define BSZ  4
#define NL   12
#define NH   8
#define DHD  64
#define DM   512
#define DI   2048
#define NV   10000
#define HD   512
#define QKV  1536

typedef __nv_bfloat16 bf16;
typedef long long ll;

// ---------------- scratch (device globals; no allocations) ----------------
__device__ bf16 g_qkvwh[9437184], g_qkvwl[9437184];
__device__ bf16 g_rnwh[3145728],  g_rnwl[3145728];
__device__ bf16 g_owh[3145728],   g_owl[3145728];
__device__ bf16 g_f1h[12582912],  g_f1l[12582912];
__device__ bf16 g_f2h[12582912],  g_f2l[12582912];
__device__ bf16 g_pwh[5120000],   g_pwl[5120000];
__device__ bf16 g_memh[25165824], g_meml[25165824];   // all-layer split mems

__device__ bf16 g_hdh[12582912],  g_hdl[12582912];
__device__ bf16 g_rh[1048576],    g_rl[1048576];
__device__ bf16 g_rkh[12582912],  g_rkl[12582912];    // ALL-layer r_head_k (batched)
__device__ bf16 g_qwh[2097152],   g_qwl[2097152];
__device__ bf16 g_qrh[2097152],   g_qrl[2097152];
__device__ float g_bd[67108864];          // pre-shifted BD: [bh][i][j]
__device__ bf16 g_vth[4194304],   g_vtl[4194304];
__device__ bf16 g_vech[2097152],  g_vecl[2097152];
__device__ float g_h[2097152],    g_tmp[2097152];
__device__ bf16 g_hh[2097152],    g_hl[2097152];
__device__ bf16 g_ffh[8388608],   g_ffl[8388608];

// ---------------- helpers ----------------
__device__ __forceinline__ uint32_t smem_u32(const void* p){
    uint32_t a;
    asm("{ .reg .u64 t; cvta.to.shared.u64 t, %1; cvt.u32.u64 %0, t; }" : "=r"(a) : "l"(p));
    return a;
}
__device__ __forceinline__ void cpasync16(uint32_t dst, const void* src, int sz){
    asm volatile("cp.async.cg.shared.global [%0], [%1], 16, %2;"
                 :: "r"(dst), "l"(src), "r"(sz) : "memory");
}
__device__ __forceinline__ void cp_commit(){
    asm volatile("cp.async.commit_group;" ::: "memory");
}
__device__ __forceinline__ void cp_wait0(){
    asm volatile("cp.async.wait_group 0;" ::: "memory");
}
__device__ __forceinline__ void cp_wait1(){
    asm volatile("cp.async.wait_group 1;" ::: "memory");
}
__device__ __forceinline__ void mma16816(float* c, const uint32_t* a, const uint32_t* b){
    asm volatile(
        "mma.sync.aligned.m16n8k16.row.col.f32.bf16.bf16.f32 "
        "{%0,%1,%2,%3}, {%4,%5,%6,%7}, {%8,%9}, {%0,%1,%2,%3};"
        : "+f"(c[0]), "+f"(c[1]), "+f"(c[2]), "+f"(c[3])
        : "r"(a[0]), "r"(a[1]), "r"(a[2]), "r"(a[3]), "r"(b[0]), "r"(b[1]));
}
__device__ __forceinline__ void split2(float v, bf16* hi, bf16* lo){
    bf16 h = __float2bfloat16(v);
    *hi = h;
    *lo = __float2bfloat16(v - __bfloat162float(h));
}
__device__ __forceinline__ void pack_split(float x, float y, uint32_t& hi, uint32_t& lo){
    bf16 hx = __float2bfloat16(x), hy = __float2bfloat16(y);
    hi = (uint32_t)__bfloat16_as_ushort(hx) | ((uint32_t)__bfloat16_as_ushort(hy) << 16);
    bf16 lx = __float2bfloat16(x - __bfloat162float(hx));
    bf16 ly = __float2bfloat16(y - __bfloat162float(hy));
    lo = (uint32_t)__bfloat16_as_ushort(lx) | ((uint32_t)__bfloat16_as_ushort(ly) << 16);
}

// ============ split-bf16 mma.sync GEMM (TM=128, BK=32, 2 CTAs/SM; TN templated) ============
// FROZEN r12 internals; TN in {128, 64}. 256 threads, 8 warps of 64x(TN/4) tiles.
// C[m,n] = sum_k A[m,k]*B[n,k]; (hi,lo) pairs, 3-term compensation.
// mode bits: 1=fp32 Cf, 2=split Chi/Clo, 4=+bias, 8=relu
// skipmode: 0 none; 2 BD pre-shift store + unread-col skip; 3 PV K clamp; 4 QKV q-tile skip
template<int TN>
__device__ __forceinline__ void load_stage32(uint32_t base,
        const bf16* __restrict__ Ah, const bf16* __restrict__ Al,
        const bf16* __restrict__ Bh, const bf16* __restrict__ Bl,
        ll lda, ll ldb, int k0, int tid, int n0, int N)
{
    const int PBA = 128*80;
    const int PBB = TN*80;
    #pragma unroll
    for (int c = tid; c < 1024; c += 256) {        // A hi/lo: 2 parts * 128 rows * 4 chunks
        int part = c >> 9;
        int r    = (c >> 2) & 127;
        int qq   = c & 3;
        uint32_t dst = base + part*PBA + r*80 + qq*16;
        const bf16* src = (part ? Al : Ah) + (ll)r*lda + k0 + qq*8;
        cpasync16(dst, src, 16);
    }
    #pragma unroll
    for (int c = tid; c < TN*8; c += 256) {        // B hi/lo: 2 parts * TN rows * 4 chunks
        int part = c / (TN*4);
        int r    = (c >> 2) % TN;
        int qq   = c & 3;
        uint32_t dst = base + 2*PBA + part*PBB + r*80 + qq*16;
        int ok = (n0 + r < N) ? 16 : 0;
        const bf16* src = (part ? Bl : Bh) + (ok ? ((ll)r*ldb + k0 + qq*8) : 0);
        cpasync16(dst, src, ok);
    }
    cp_commit();
}

template<int TN>
__global__ void __launch_bounds__(256, 2)
k_gemm(const bf16* __restrict__ Ahi, const bf16* __restrict__ Alo,
       const bf16* __restrict__ A2h, const bf16* __restrict__ A2l, int splitM,
       ll lda, ll aq, ll ar,
       const bf16* __restrict__ Bhi, const bf16* __restrict__ Blo, ll ldb, ll bq, ll br,
       float* __restrict__ Cf, bf16* __restrict__ Chi, bf16* __restrict__ Clo, ll ldc, ll cq, ll cr,
       const float* __restrict__ bias, int N, int K, int ZD, int mode, int skipmode)
{
    extern __shared__ char dsm[];
    const int PBA = 128*80;
    const int PBB = TN*80;
    const int STG = 2*PBA + 2*PBB;
    const int NT  = TN/32;
    const int WNS = TN/4;

    int m0 = blockIdx.y << 7;
    int n0 = blockIdx.x * TN;

    if (skipmode == 2 && n0 < 769 - m0) return;        // never-read raw BD columns
    if (skipmode == 4 && n0 < 512 && m0 < 4096) return; // q outputs for mem rows: never read
    int nKb = K >> 5;
    if (skipmode == 3) {
        int lim = ((m0 + 1151) >> 5) + 1;              // probs zero beyond j = i_max + MLEN
        if (lim < nKb) nKb = lim;
    }

    uint32_t sb = smem_u32(dsm);
    int tid  = threadIdx.x;
    int wid  = tid >> 5, lane = tid & 31;
    int wm   = wid >> 2;
    int wn   = wid & 3;
    int tg   = lane >> 2, tq = lane & 3;

    int z  = blockIdx.z;
    ll offA = (ll)(z / ZD) * aq + (ll)(z % ZD) * ar;
    ll offB = (ll)(z / ZD) * bq + (ll)(z % ZD) * br;
    ll offC = (ll)(z / ZD) * cq + (ll)(z % ZD) * cr;

    const bf16* Asrc_h = Ahi;
    const bf16* Asrc_l = Alo;
    int mrow = m0;
    if (splitM > 0 && m0 >= splitM) { Asrc_h = A2h; Asrc_l = A2l; mrow = m0 - splitM; }
    const bf16* Ah = Asrc_h + offA + (ll)mrow * lda;
    const bf16* Al = Asrc_l + offA + (ll)mrow * lda;
    const bf16* Bh = Bhi + offB + (ll)n0 * ldb;
    const bf16* Bl = Blo + offB + (ll)n0 * ldb;

    float acc[4][NT][4];
    #pragma unroll
    for (int i = 0; i < 4; i++)
        #pragma unroll
        for (int j = 0; j < NT; j++)
            #pragma unroll
            for (int r = 0; r < 4; r++) acc[i][j][r] = 0.f;

    load_stage32<TN>(sb, Ah, Al, Bh, Bl, lda, ldb, 0, tid, n0, N);

    for (int kb = 0; kb < nKb; kb++) {
        if (kb + 1 < nKb) {
            load_stage32<TN>(sb + ((kb+1)&1)*STG, Ah, Al, Bh, Bl, lda, ldb,
                             (kb+1) << 5, tid, n0, N);
            cp_wait1();
        } else {
            cp_wait0();
        }
        __syncthreads();

        const uint32_t* As = (const uint32_t*)(dsm + (kb&1)*STG);
        const uint32_t* Bs = (const uint32_t*)(dsm + (kb&1)*STG + 2*PBA);
        const int AP = PBA/4, BP = PBB/4;

        #pragma unroll
        for (int kk = 0; kk < 2; kk++) {
            uint32_t a_h[4][4], a_l[4][4], b_h[NT][2], b_l[NT][2];
            int kw = kk*8 + tq;
            #pragma unroll
            for (int mt = 0; mt < 4; mt++) {
                int r0 = (wm*64 + mt*16 + tg) * 20;
                int r1 = r0 + 8*20;
                a_h[mt][0] = As[r0 + kw];      a_h[mt][1] = As[r1 + kw];
                a_h[mt][2] = As[r0 + kw + 4];  a_h[mt][3] = As[r1 + kw + 4];
                a_l[mt][0] = As[AP + r0 + kw];     a_l[mt][1] = As[AP + r1 + kw];
                a_l[mt][2] = As[AP + r0 + kw + 4]; a_l[mt][3] = As[AP + r1 + kw + 4];
            }
            #pragma unroll
            for (int nt = 0; nt < NT; nt++) {
                int nr = (wn*WNS + nt*8 + tg) * 20;
                b_h[nt][0] = Bs[nr + kw];      b_h[nt][1] = Bs[nr + kw + 4];
                b_l[nt][0] = Bs[BP + nr + kw]; b_l[nt][1] = Bs[BP + nr + kw + 4];
            }
            #pragma unroll
            for (int mt = 0; mt < 4; mt++)
                #pragma unroll
                for (int nt = 0; nt < NT; nt++) {
                    mma16816(acc[mt][nt], a_h[mt], b_h[nt]);
                    mma16816(acc[mt][nt], a_h[mt], b_l[nt]);
                    mma16816(acc[mt][nt], a_l[mt], b_h[nt]);
                }
        }
        __syncthreads();
    }

    // epilogue (vectorized: 2 consecutive n per store)
    #pragma unroll
    for (int mt = 0; mt < 4; mt++) {
        #pragma unroll
        for (int nt = 0; nt < NT; nt++) {
            int n = n0 + wn*WNS + nt*8 + tq*2;
            if (n >= N) continue;
            float b0 = 0.f, b1 = 0.f;
            if (mode & 4) { b0 = bias[n]; b1 = bias[n+1]; }
            #pragma unroll
            for (int half = 0; half < 2; half++) {
                int m = m0 + wm*64 + mt*16 + tg + half*8;
                float v0 = acc[mt][nt][half*2]     + b0;
                float v1 = acc[mt][nt][half*2 + 1] + b1;
                if (mode & 8) { v0 = fmaxf(v0, 0.f); v1 = fmaxf(v1, 0.f); }
                if (skipmode == 2) {
                    int j = n - 1023 + m;       // pre-shifted column
                    float* row = Cf + offC + (ll)m * ldc;
                    if (j >= 0)     row[j]     = v0;
                    if (j + 1 >= 0) row[j + 1] = v1;
                    continue;
                }
                ll cidx = offC + (ll)m * ldc + n;
                if (mode & 1) *(float2*)(Cf + cidx) = make_float2(v0, v1);
                if (mode & 2) {
                    uint32_t hi, lo;
                    pack_split(v0, v1, hi, lo);
                    *(uint32_t*)(Chi + cidx) = hi;
                    *(uint32_t*)(Clo + cidx) = lo;
                }
            }
        }
    }
}

// ================= fused flash attention =================
__device__ __forceinline__ void flash_load_kv(uint32_t base,
        const bf16* __restrict__ Kh, const bf16* __restrict__ Kl,
        const bf16* __restrict__ Vh, const bf16* __restrict__ Vl,
        int j0, int tid)
{
    #pragma unroll
    for (int c = tid; c < 2048; c += 256) {
        int t4 = c >> 9;           // 0 Kh, 1 Kl, 2 Vh, 3 Vl
        int r  = (c >> 3) & 63;
        int qq = c & 7;
        uint32_t dst = base + t4*9216 + r*144 + qq*16;
        const bf16* src;
        if (t4 == 0)      src = Kh + (ll)(j0 + r)*6144 + qq*8;
        else if (t4 == 1) src = Kl + (ll)(j0 + r)*6144 + qq*8;
        else if (t4 == 2) src = Vh + (ll)r*2048 + j0 + qq*8;
        else              src = Vl + (ll)r*2048 + j0 + qq*8;
        cpasync16(dst, src, 16);
    }
    cp_commit();
}

__global__ void __launch_bounds__(256, 1)
k_flash(const bf16* __restrict__ qh_, const bf16* __restrict__ ql_,
        const bf16* __restrict__ kh_, const bf16* __restrict__ kl_,
        const bf16* __restrict__ vh_, const bf16* __restrict__ vl_,
        const float* __restrict__ bd_,
        bf16* __restrict__ voh, bf16* __restrict__ vol)
{
    extern __shared__ char sm[];
    const int QLO = 0, QLL = 18432, ST0 = 36864, STSZ = 36864;

    int tid = threadIdx.x, wid = tid >> 5, lane = tid & 31;
    int tg = lane >> 2, tq = lane & 3;
    int i0 = (7 - (int)blockIdx.x) << 7;   // heavy causal blocks scheduled first
    int z  = blockIdx.y;
    int b = z >> 3, h_ = z & 7;
    uint32_t sb = smem_u32(sm);

    const bf16* Qh = qh_ + (ll)z*65536 + (ll)i0*64;
    const bf16* Ql = ql_ + (ll)z*65536 + (ll)i0*64;
    const bf16* Kh = kh_ + (ll)b*1536 + h_*64;
    const bf16* Kl = kl_ + (ll)b*1536 + h_*64;
    const bf16* Vh = vh_ + (ll)z*131072;
    const bf16* Vl = vl_ + (ll)z*131072;
    const float* BD = bd_ + (ll)z*2097152;

    #pragma unroll
    for (int c = tid; c < 2048; c += 256) {
        int part = c >> 10, r = (c >> 3) & 127, qq = c & 7;
        cpasync16(sb + (part ? QLL : QLO) + r*144 + qq*16,
                  (part ? Ql : Qh) + (ll)r*64 + qq*8, 16);
    }
    cp_commit();

    int jbmax = ((i0 + 127 + MLEN) >> 6) + 1;
    if (jbmax > 32) jbmax = 32;
    flash_load_kv(sb + ST0, Kh, Kl, Vh, Vl, 0, tid);

    float O[8][4];
    #pragma unroll
    for (int dt = 0; dt < 8; dt++) { O[dt][0]=O[dt][1]=O[dt][2]=O[dt][3]=0.f; }
    float mA = -1e30f, mB = -1e30f, lA = 0.f, lB = 0.f;
    int riA = i0 + wid*16 + tg, riB = riA + 8;

    const uint32_t* Qsh = (const uint32_t*)(sm + QLO);
    const uint32_t* Qsl = (const uint32_t*)(sm + QLL);
    const float* BDrA = BD + (ll)riA*2048;
    const float* BDrB = BD + (ll)riB*2048;

    for (int jb = 0; jb < jbmax; jb++) {
        int s = jb & 1;
        if (jb + 1 < jbmax) {
            flash_load_kv(sb + ST0 + (s^1)*STSZ, Kh, Kl, Vh, Vl, (jb+1) << 6, tid);
            cp_wait1();
        } else {
            cp_wait0();
        }
        __syncthreads();

        const uint32_t* Ksh = (const uint32_t*)(sm + ST0 + s*STSZ);
        const uint32_t* Ksl = Ksh + 2304;
        const uint32_t* Vsh = Ksh + 4608;
        const uint32_t* Vsl = Ksh + 6912;
        int j0 = jb << 6;

        float S[8][4];
        #pragma unroll
        for (int nt = 0; nt < 8; nt++) { S[nt][0]=S[nt][1]=S[nt][2]=S[nt][3]=0.f; }

        #pragma unroll
        for (int kt = 0; kt < 4; kt++) {
            int kw = kt*8 + tq;
            int r0 = (wid*16 + tg) * 36, r1 = r0 + 8*36;
            uint32_t ah[4], al[4];
            ah[0]=Qsh[r0+kw]; ah[1]=Qsh[r1+kw]; ah[2]=Qsh[r0+kw+4]; ah[3]=Qsh[r1+kw+4];
            al[0]=Qsl[r0+kw]; al[1]=Qsl[r1+kw]; al[2]=Qsl[r0+kw+4]; al[3]=Qsl[r1+kw+4];
            #pragma unroll
            for (int nt = 0; nt < 8; nt++) {
                int nr = (nt*8 + tg) * 36;
                uint32_t bh2[2], bl2[2];
                bh2[0]=Ksh[nr+kw]; bh2[1]=Ksh[nr+kw+4];
                bl2[0]=Ksl[nr+kw]; bl2[1]=Ksl[nr+kw+4];
                mma16816(S[nt], ah, bh2);
                mma16816(S[nt], ah, bl2);
                mma16816(S[nt], al, bh2);
            }
        }

        float bmA = -1e30f, bmB = -1e30f;
        #pragma unroll
        for (int nt = 0; nt < 8; nt++) {
            int j = j0 + nt*8 + 2*tq;
            float2 bA = *(const float2*)(BDrA + j);
            float2 bB = *(const float2*)(BDrB + j);
            S[nt][0] = (j     <= riA + MLEN) ? (S[nt][0] + bA.x)*0.125f : -1e30f;
            S[nt][1] = (j + 1 <= riA + MLEN) ? (S[nt][1] + bA.y)*0.125f : -1e30f;
            S[nt][2] = (j     <= riB + MLEN) ? (S[nt][2] + bB.x)*0.125f : -1e30f;
            S[nt][3] = (j + 1 <= riB + MLEN) ? (S[nt][3] + bB.y)*0.125f : -1e30f;
            bmA = fmaxf(bmA, fmaxf(S[nt][0], S[nt][1]));
            bmB = fmaxf(bmB, fmaxf(S[nt][2], S[nt][3]));
        }
        bmA = fmaxf(bmA, __shfl_xor_sync(0xffffffffu, bmA, 1));
        bmA = fmaxf(bmA, __shfl_xor_sync(0xffffffffu, bmA, 2));
        bmB = fmaxf(bmB, __shfl_xor_sync(0xffffffffu, bmB, 1));
        bmB = fmaxf(bmB, __shfl_xor_sync(0xffffffffu, bmB, 2));
        float mAn = fmaxf(mA, bmA), mBn = fmaxf(mB, bmB);
        float aAs = __expf(mA - mAn), aBs = __expf(mB - mBn);

        float sA = 0.f, sB = 0.f;
        #pragma unroll
        for (int nt = 0; nt < 8; nt++) {
            S[nt][0] = __expf(S[nt][0] - mAn);
            S[nt][1] = __expf(S[nt][1] - mAn);
            S[nt][2] = __expf(S[nt][2] - mBn);
            S[nt][3] = __expf(S[nt][3] - mBn);
            sA += S[nt][0] + S[nt][1];
            sB += S[nt][2] + S[nt][3];
            O[nt][0] *= aAs; O[nt][1] *= aAs; O[nt][2] *= aBs; O[nt][3] *= aBs;
        }
        sA += __shfl_xor_sync(0xffffffffu, sA, 1);
        sA += __shfl_xor_sync(0xffffffffu, sA, 2);
        sB += __shfl_xor_sync(0xffffffffu, sB, 1);
        sB += __shfl_xor_sync(0xffffffffu, sB, 2);
        lA = lA*aAs + sA; lB = lB*aBs + sB;
        mA = mAn; mB = mBn;

        #pragma unroll
        for (int kt = 0; kt < 4; kt++) {
            uint32_t pah[4], pal[4];
            pack_split(S[2*kt][0],   S[2*kt][1],   pah[0], pal[0]);
            pack_split(S[2*kt][2],   S[2*kt][3],   pah[1], pal[1]);
            pack_split(S[2*kt+1][0], S[2*kt+1][1], pah[2], pal[2]);
            pack_split(S[2*kt+1][2], S[2*kt+1][3], pah[3], pal[3]);
            int kw = kt*8 + tq;
            #pragma unroll
            for (int dt = 0; dt < 8; dt++) {
                int nr = (dt*8 + tg) * 36;
                uint32_t bh2[2], bl2[2];
                bh2[0]=Vsh[nr+kw]; bh2[1]=Vsh[nr+kw+4];
                bl2[0]=Vsl[nr+kw]; bl2[1]=Vsl[nr+kw+4];
                mma16816(O[dt], pah, bh2);
                mma16816(O[dt], pah, bl2);
                mma16816(O[dt], pal, bh2);
            }
        }
        __syncthreads();
    }

    float ivA = 1.f/lA, ivB = 1.f/lB;
    #pragma unroll
    for (int dt = 0; dt < 8; dt++) {
        int d0 = dt*8 + 2*tq;
        ll aA = (ll)riA*2048 + b*512 + h_*64 + d0;
        ll aB = (ll)riB*2048 + b*512 + h_*64 + d0;
        uint32_t hi, lo;
        pack_split(O[dt][0]*ivA, O[dt][1]*ivA, hi, lo);
        *(uint32_t*)(voh + aA) = hi; *(uint32_t*)(vol + aA) = lo;
        pack_split(O[dt][2]*ivB, O[dt][3]*ivB, hi, lo);
        *(uint32_t*)(voh + aB) = hi; *(uint32_t*)(vol + aB) = lo;
    }
}

// ================= elementwise / small kernels =================
__global__ void k_split(const float4* __restrict__ in, uint2* __restrict__ hi,
                        uint2* __restrict__ lo, ll n4){
    ll i = (ll)blockIdx.x * blockDim.x + threadIdx.x;
    if (i >= n4) return;
    float4 v = in[i];
    uint32_t h0,l0,h1,l1;
    pack_split(v.x, v.y, h0, l0);
    pack_split(v.z, v.w, h1, l1);
    hi[i] = make_uint2(h0, h1);
    lo[i] = make_uint2(l0, l1);
}

__global__ void k_embed(const int* __restrict__ x, const float* __restrict__ emb,
                        float* __restrict__ h, bf16* __restrict__ hh, bf16* __restrict__ hl)
{
    int idx = blockIdx.x * blockDim.x + threadIdx.x;
    if (idx >= QLEN*BSZ*DM) return;
    int d = idx & (DM-1);
    int b = (idx >> 9) & 3;
    int i = idx >> 11;
    int tok = x[i*BSZ + b];
    float v = emb[(ll)tok*DM + d] * 22.627416997969522f;
    h[idx] = v;
    split2(v, hh + idx, hl + idx);
}

__global__ void k_posemb(bf16* __restrict__ rh, bf16* __restrict__ rl)
{
    int idx = blockIdx.x * blockDim.x + threadIdx.x;
    if (idx >= KLEN*DM) return;
    int d = idx & (DM-1);
    int k = idx >> 9;
    double pos = (double)(KLEN - 1 - k);
    int t = (d < 256) ? d : d - 256;
    double f = exp(-(double)t * (log(10000.0) / 256.0));
    double a = pos * f;
    float v = (float)((d < 256) ? sin(a) : cos(a));
    split2(v, rh + idx, rl + idx);
}

// q + biases, re-split into [bh][i][64]
__global__ void k_qbias(const bf16* __restrict__ hh, const bf16* __restrict__ hl,
                        const float* __restrict__ rwb, const float* __restrict__ rrb,
                        bf16* __restrict__ qwh, bf16* __restrict__ qwl,
                        bf16* __restrict__ qrh, bf16* __restrict__ qrl)
{
    int idx = blockIdx.x * blockDim.x + threadIdx.x;
    if (idx >= 32*1024*64) return;
    int d = idx & 63;
    int i = (idx >> 6) & 1023;
    int z = idx >> 16;
    int b = z >> 3, h_ = z & 7;
    ll src = ((ll)(MLEN + i)*BSZ + b)*QKV + h_*64 + d;
    float q = __bfloat162float(hh[src]) + __bfloat162float(hl[src]);
    split2(q + rwb[h_*64 + d], qwh + idx, qwl + idx);
    split2(q + rrb[h_*64 + d], qrh + idx, qrl + idx);
}

__global__ void k_vtrans(const bf16* __restrict__ hh, const bf16* __restrict__ hl,
                         bf16* __restrict__ vth, bf16* __restrict__ vtl)
{
    __shared__ bf16 th[64][65], tl[64][65];
    int z = blockIdx.y;
    int j0 = blockIdx.x << 6;
    int b = z >> 3, h_ = z & 7;
    #pragma unroll
    for (int p = 0; p < 16; p++) {
        int jj = (threadIdx.x >> 6) + p*4;
        int d  = threadIdx.x & 63;
        ll src = ((ll)(j0 + jj)*BSZ + b)*QKV + 1024 + h_*64 + d;
        th[jj][d] = hh[src];
        tl[jj][d] = hl[src];
    }
    __syncthreads();
    #pragma unroll
    for (int p = 0; p < 16; p++) {
        int dd = (threadIdx.x >> 6) + p*4;
        int j  = threadIdx.x & 63;
        ll dst = (ll)z*131072 + (ll)dd*2048 + j0 + j;
        vth[dst] = th[j][dd];
        vtl[dst] = tl[j][dd];
    }
}

__global__ void __launch_bounds__(256)
k_add_ln(float* __restrict__ h, const float* __restrict__ res,
         const float* __restrict__ g, const float* __restrict__ be,
         bf16* __restrict__ hh, bf16* __restrict__ hl)
{
    int row = blockIdx.x;
    int tid = threadIdx.x;
    int lane = tid & 31, wid = tid >> 5;
    __shared__ float red[8];
    __shared__ float s_mean, s_rstd;

    float* hp = h + (ll)row*DM;
    const float* rp = res + (ll)row*DM;

    float v0 = hp[tid]       + rp[tid];
    float v1 = hp[tid + 256] + rp[tid + 256];

    float s = v0 + v1;
    #pragma unroll
    for (int o = 16; o > 0; o >>= 1) s += __shfl_xor_sync(0xffffffffu, s, o);
    if (lane == 0) red[wid] = s;
    __syncthreads();
    if (wid == 0) {
        float t = (lane < 8) ? red[lane] : 0.f;
        #pragma unroll
        for (int o = 4; o > 0; o >>= 1) t += __shfl_xor_sync(0xffffffffu, t, o);
        if (lane == 0) s_mean = t * (1.0f/512.0f);
    }
    __syncthreads();
    float mean = s_mean;
    float d0 = v0 - mean, d1 = v1 - mean;

    s = d0*d0 + d1*d1;
    #pragma unroll
    for (int o = 16; o > 0; o >>= 1) s += __shfl_xor_sync(0xffffffffu, s, o);
    if (lane == 0) red[wid] = s;
    __syncthreads();
    if (wid == 0) {
        float t = (lane < 8) ? red[lane] : 0.f;
        #pragma unroll
        for (int o = 4; o > 0; o >>= 1) t += __shfl_xor_sync(0xffffffffu, t, o);
        if (lane == 0) s_rstd = rsqrtf(t * (1.0f/512.0f) + 1e-5f);
    }
    __syncthreads();
    float rs = s_rstd;

    float o0 = d0 * rs * g[tid]       + be[tid];
    float o1 = d1 * rs * g[tid + 256] + be[tid + 256];
    hp[tid]       = o0;
    hp[tid + 256] = o1;
    ll base = (ll)row*DM;
    split2(o0, hh + base + tid,       hl + base + tid);
    split2(o1, hh + base + tid + 256, hl + base + tid + 256);
}

// ================= host =================
static const int SMGEMM128 = 2*(2*128*80 + 2*128*80);  // 81920
static const int SMGEMM64  = 2*(2*128*80 + 2*64*80);   // 61440
static const int SMFLSH    = 36864 + 2*36864;          // 110592

extern "C" void kernel_launch(void* const* d_in, const int* in_sizes, int n_in,
                              void* d_out, int out_size)
{
    const int*   x        = (const int*)  d_in[0];
    const float* mems     = (const float*)d_in[1];
    const float* emb      = (const float*)d_in[2];
    const float* qkv_w    = (const float*)d_in[3];
    const float* r_net_w  = (const float*)d_in[4];
    const float* o_w      = (const float*)d_in[5];
    const float* ln1_g    = (const float*)d_in[6];
    const float* ln1_b    = (const float*)d_in[7];
    const float* ff_w1    = (const float*)d_in[8];
    const float* ff_b1    = (const float*)d_in[9];
    const float* ff_w2    = (const float*)d_in[10];
    const float* ff_b2    = (const float*)d_in[11];
    const float* ln2_g    = (const float*)d_in[12];
    const float* ln2_b    = (const float*)d_in[13];
    const float* r_w_bias = (const float*)d_in[14];
    const float* r_r_bias = (const float*)d_in[15];
    const float* proj_w   = (const float*)d_in[16];
    const float* proj_b   = (const float*)d_in[17];
    float* out = (float*)d_out;

    static bool attr_done = false;
    if (!attr_done) {
        cudaFuncSetAttribute(k_gemm<128>, cudaFuncAttributeMaxDynamicSharedMemorySize, SMGEMM128);
        cudaFuncSetAttribute(k_gemm<64>,  cudaFuncAttributeMaxDynamicSharedMemorySize, SMGEMM64);
        cudaFuncSetAttribute(k_flash,     cudaFuncAttributeMaxDynamicSharedMemorySize, SMFLSH);
        attr_done = true;
    }

    bf16 *qkvwh,*qkvwl,*rnwh,*rnwl,*owh,*owl,*f1h,*f1l,*f2h,*f2l,*pwh,*pwl,*memh,*meml;
    bf16 *hdh,*hdl,*rh,*rl,*rkh,*rkl,*qwh,*qwl,*qrh,*qrl;
    bf16 *vth,*vtl,*vech,*vecl,*hh,*hl,*ffh,*ffl;
    float *bd,*h,*tmp;
    cudaGetSymbolAddress((void**)&qkvwh, g_qkvwh); cudaGetSymbolAddress((void**)&qkvwl, g_qkvwl);
    cudaGetSymbolAddress((void**)&rnwh,  g_rnwh);  cudaGetSymbolAddress((void**)&rnwl,  g_rnwl);
    cudaGetSymbolAddress((void**)&owh,   g_owh);   cudaGetSymbolAddress((void**)&owl,   g_owl);
    cudaGetSymbolAddress((void**)&f1h,   g_f1h);   cudaGetSymbolAddress((void**)&f1l,   g_f1l);
    cudaGetSymbolAddress((void**)&f2h,   g_f2h);   cudaGetSymbolAddress((void**)&f2l,   g_f2l);
    cudaGetSymbolAddress((void**)&pwh,   g_pwh);   cudaGetSymbolAddress((void**)&pwl,   g_pwl);
    cudaGetSymbolAddress((void**)&memh,  g_memh);  cudaGetSymbolAddress((void**)&meml,  g_meml);
    cudaGetSymbolAddress((void**)&hdh,   g_hdh);   cudaGetSymbolAddress((void**)&hdl,   g_hdl);
    cudaGetSymbolAddress((void**)&rh,    g_rh);    cudaGetSymbolAddress((void**)&rl,    g_rl);
    cudaGetSymbolAddress((void**)&rkh,   g_rkh);   cudaGetSymbolAddress((void**)&rkl,   g_rkl);
    cudaGetSymbolAddress((void**)&qwh,   g_qwh);   cudaGetSymbolAddress((void**)&qwl,   g_qwl);
    cudaGetSymbolAddress((void**)&qrh,   g_qrh);   cudaGetSymbolAddress((void**)&qrl,   g_qrl);
    cudaGetSymbolAddress((void**)&vth,   g_vth);   cudaGetSymbolAddress((void**)&vtl,   g_vtl);
    cudaGetSymbolAddress((void**)&vech,  g_vech);  cudaGetSymbolAddress((void**)&vecl,  g_vecl);
    cudaGetSymbolAddress((void**)&hh,    g_hh);    cudaGetSymbolAddress((void**)&hl,    g_hl);
    cudaGetSymbolAddress((void**)&ffh,   g_ffh);   cudaGetSymbolAddress((void**)&ffl,   g_ffl);
    cudaGetSymbolAddress((void**)&bd,    g_bd);
    cudaGetSymbolAddress((void**)&h,     g_h);     cudaGetSymbolAddress((void**)&tmp,   g_tmp);

    const int NTOK = QLEN*BSZ;

    k_split<<<(2359296 +255)/256, 256>>>((const float4*)qkv_w, (uint2*)qkvwh, (uint2*)qkvwl, 2359296LL);
    k_embed <<<(QLEN*BSZ*DM + 255)/256, 256>>>(x, emb, h, hh, hl);
    k_split<<<(6291456 +255)/256, 256>>>((const float4*)mems, (uint2*)memh, (uint2*)meml, 6291456LL);

    // #4 (ncu capture slot): layer-0 QKV GEMM
    k_gemm<128><<<dim3(12, 64, 1), 256, SMGEMM128>>>(
        memh, meml, hh, hl, 4096,
        512, 0, 0,
        qkvwh, qkvwl, 512, 0, 0,
        nullptr, hdh, hdl, 1536, 0, 0,
        nullptr, 1536, 512, 1, 2, 4);

    k_posemb<<<(KLEN*DM + 255)/256, 256>>>(rh, rl);
    k_split<<<(786432  +255)/256, 256>>>((const float4*)r_net_w, (uint2*)rnwh, (uint2*)rnwl, 786432LL);

    // ALL-layer rhk in ONE batched GEMM: rk[l] = r x r_net_w[l]^T  (z = layer)
    k_gemm<128><<<dim3(4, 16, 12), 256, SMGEMM128>>>(
        rh, rl, nullptr, nullptr, 0,
        512, 0, 0,
        rnwh, rnwl, 512, 262144, 0,
        nullptr, rkh, rkl, 512, 1048576, 0,
        nullptr, 512, 512, 1, 2, 0);

    k_split<<<(786432  +255)/256, 256>>>((const float4*)o_w,    (uint2*)owh, (uint2*)owl, 786432LL);
    k_split<<<(3145728 +255)/256, 256>>>((const float4*)ff_w1,  (uint2*)f1h, (uint2*)f1l, 3145728LL);
    k_split<<<(3145728 +255)/256, 256>>>((const float4*)ff_w2,  (uint2*)f2h, (uint2*)f2l, 3145728LL);
    k_split<<<(1280000 +255)/256, 256>>>((const float4*)proj_w, (uint2*)pwh, (uint2*)pwl, 1280000LL);

    for (int l = 0; l < NL; l++) {
        if (l > 0) {
            k_gemm<128><<<dim3(12, 64, 1), 256, SMGEMM128>>>(
                memh + (ll)l*2097152, meml + (ll)l*2097152, hh, hl, 4096,
                512, 0, 0,
                qkvwh + (ll)l*786432, qkvwl + (ll)l*786432, 512, 0, 0,
                nullptr, hdh, hdl, 1536, 0, 0,
                nullptr, 1536, 512, 1, 2, 4);
        }

        // q + biases
        k_qbias<<<(32*1024*64 + 255)/256, 256>>>(hdh, hdl, r_w_bias, r_r_bias, qwh, qwl, qrh, qrl);

        // BD raw -> PRE-SHIFTED store (skipmode 2); rhk from batched buffer
        k_gemm<128><<<dim3(16, 8, 32), 256, SMGEMM128>>>(
            qrh, qrl, nullptr, nullptr, 0,
            64, 8LL*65536, 65536,
            rkh + (ll)l*1048576, rkl + (ll)l*1048576, 512, 0, 64,
            bd, nullptr, nullptr, 2048, 8LL*2097152, 2097152,
            nullptr, 2048, 64, 8, 1, 2);

        // V transpose
        k_vtrans<<<dim3(32, 32), 256>>>(hdh, hdl, vth, vtl);

        // fused AC + BDshift + mask + softmax + PV (heavy-first CTA order)
        k_flash<<<dim3(8, 32), 256, SMFLSH>>>(
            qwh, qwl, hdh + 512, hdl + 512, vth, vtl, bd, vech, vecl);

        // attn_out = vec x o_w^T -> fp32 tmp  (TN=64: 256 CTAs, better chip fill)
        k_gemm<64><<<dim3(8, 32, 1), 256, SMGEMM64>>>(
            vech, vecl, nullptr, nullptr, 0,
            512, 0, 0,
            owh + (ll)l*262144, owl + (ll)l*262144, 512, 0, 0,
            tmp, nullptr, nullptr, 512, 0, 0,
            nullptr, 512, 512, 1, 1, 0);

        k_add_ln<<<NTOK, 256>>>(h, tmp, ln1_g + l*DM, ln1_b + l*DM, hh, hl);

        // ff = relu(h x ff_w1^T + b1)
        k_gemm<128><<<dim3(16, 32, 1), 256, SMGEMM128>>>(
            hh, hl, nullptr, nullptr, 0,
            512, 0, 0,
            f1h + (ll)l*1048576, f1l + (ll)l*1048576, 512, 0, 0,
            nullptr, ffh, ffl, 2048, 0, 0,
            ff_b1 + (ll)l*DI, 2048, 512, 1, 2|4|8, 0);

        // tmp = ff x ff_w2^T + b2  (TN=64: 256 CTAs, better chip fill)
        k_gemm<64><<<dim3(8, 32, 1), 256, SMGEMM64>>>(
            ffh, ffl, nullptr, nullptr, 0,
            2048, 0, 0,
            f2h + (ll)l*1048576, f2l + (ll)l*1048576, 2048, 0, 0,
            tmp, nullptr, nullptr, 512, 0, 0,
            ff_b2 + (ll)l*DM, 512, 2048, 1, 1|4, 0);

        k_add_ln<<<NTOK, 256>>>(h, tmp, ln2_g + l*DM, ln2_b + l*DM, hh, hl);
    }

    // logits = h x proj_w^T + proj_b
    k_gemm<128><<<dim3(79, 32, 1), 256, SMGEMM128>>>(
        hh, hl, nullptr, nullptr, 0,
        512, 0, 0,
        pwh, pwl, 512, 0, 0,
        out, nullptr, nullptr, 10000, 0, 0,
        proj_b, 10000, 512, 1, 1|4, 0);
}

// round 16
// speedup vs baseline: 1.0343x; 1.0343x over previous
#include <cuda_runtime.h>
#include <cuda_bf16.h>
#include <math.h>
#include <stdint.h>

#define QLEN 1024
#define MLEN 1024
#define KLEN 2048
#define BSZ  4
#define NL   12
#define NH   8
#define DHD  64
#define DM   512
#define DI   2048
#define NV   10000
#define HD   512
#define QKV  1536

typedef __nv_bfloat16 bf16;
typedef long long ll;

// ---------------- scratch (device globals; no allocations) ----------------
__device__ bf16 g_qkvwh[9437184], g_qkvwl[9437184];
__device__ bf16 g_rnwh[3145728],  g_rnwl[3145728];
__device__ bf16 g_owh[3145728],   g_owl[3145728];
__device__ bf16 g_f1h[12582912],  g_f1l[12582912];
__device__ bf16 g_f2h[12582912],  g_f2l[12582912];
__device__ bf16 g_pwh[5120000],   g_pwl[5120000];
__device__ bf16 g_memh[25165824], g_meml[25165824];   // all-layer split mems

__device__ bf16 g_hdh[12582912],  g_hdl[12582912];
__device__ bf16 g_rh[1048576],    g_rl[1048576];
__device__ bf16 g_rkh[12582912],  g_rkl[12582912];    // ALL-layer r_head_k (batched)
__device__ bf16 g_qwh[2097152],   g_qwl[2097152];
__device__ bf16 g_qrh[2097152],   g_qrl[2097152];
__device__ float g_bd[67108864];          // pre-shifted BD: [bh][i][j]
__device__ bf16 g_vth[4194304],   g_vtl[4194304];
__device__ bf16 g_vech[2097152],  g_vecl[2097152];
__device__ float g_h[2097152],    g_tmp[4194304];     // 2 split-K partial buffers
__device__ bf16 g_hh[2097152],    g_hl[2097152];
__device__ bf16 g_ffh[8388608],   g_ffl[8388608];

// ---------------- helpers ----------------
__device__ __forceinline__ uint32_t smem_u32(const void* p){
    uint32_t a;
    asm("{ .reg .u64 t; cvta.to.shared.u64 t, %1; cvt.u32.u64 %0, t; }" : "=r"(a) : "l"(p));
    return a;
}
__device__ __forceinline__ void cpasync16(uint32_t dst, const void* src, int sz){
    asm volatile("cp.async.cg.shared.global [%0], [%1], 16, %2;"
                 :: "r"(dst), "l"(src), "r"(sz) : "memory");
}
__device__ __forceinline__ void cp_commit(){
    asm volatile("cp.async.commit_group;" ::: "memory");
}
__device__ __forceinline__ void cp_wait0(){
    asm volatile("cp.async.wait_group 0;" ::: "memory");
}
__device__ __forceinline__ void cp_wait1(){
    asm volatile("cp.async.wait_group 1;" ::: "memory");
}
__device__ __forceinline__ void mma16816(float* c, const uint32_t* a, const uint32_t* b){
    asm volatile(
        "mma.sync.aligned.m16n8k16.row.col.f32.bf16.bf16.f32 "
        "{%0,%1,%2,%3}, {%4,%5,%6,%7}, {%8,%9}, {%0,%1,%2,%3};"
        : "+f"(c[0]), "+f"(c[1]), "+f"(c[2]), "+f"(c[3])
        : "r"(a[0]), "r"(a[1]), "r"(a[2]), "r"(a[3]), "r"(b[0]), "r"(b[1]));
}
__device__ __forceinline__ void split2(float v, bf16* hi, bf16* lo){
    bf16 h = __float2bfloat16(v);
    *hi = h;
    *lo = __float2bfloat16(v - __bfloat162float(h));
}
__device__ __forceinline__ void pack_split(float x, float y, uint32_t& hi, uint32_t& lo){
    bf16 hx = __float2bfloat16(x), hy = __float2bfloat16(y);
    hi = (uint32_t)__bfloat16_as_ushort(hx) | ((uint32_t)__bfloat16_as_ushort(hy) << 16);
    bf16 lx = __float2bfloat16(x - __bfloat162float(hx));
    bf16 ly = __float2bfloat16(y - __bfloat162float(hy));
    lo = (uint32_t)__bfloat16_as_ushort(lx) | ((uint32_t)__bfloat16_as_ushort(ly) << 16);
}

// ================= split-bf16 mma.sync GEMM (128x128 tile, BK=32, 2 CTAs/SM) =================
// FROZEN r12/r14 engine. C[m,n] = sum_k A[m,k]*B[n,k]; (hi,lo) pairs, 3-term compensation.
// Split-K usage: ZD=1, aq=bq=K/2 (element offset into the K window), cq = output buffer stride.
// Bias is applied only by blockIdx.z == 0 (split-K partials must not double-count it).
// mode bits: 1=fp32 Cf, 2=split Chi/Clo, 4=+bias, 8=relu
// skipmode: 0 none; 2 BD pre-shift store + unread-col skip; 3 PV K clamp; 4 QKV q-tile skip
__device__ __forceinline__ void load_stage32(uint32_t base,
        const bf16* __restrict__ Ah, const bf16* __restrict__ Al,
        const bf16* __restrict__ Bh, const bf16* __restrict__ Bl,
        ll lda, ll ldb, int k0, int tid, int n0, int N)
{
    const int PB = 128*80;   // bytes per matrix part
    #pragma unroll
    for (int c = tid; c < 1024; c += 256) {        // A hi/lo
        int part = c >> 9;
        int r    = (c >> 2) & 127;
        int qq   = c & 3;
        uint32_t dst = base + part*PB + r*80 + qq*16;
        const bf16* src = (part ? Al : Ah) + (ll)r*lda + k0 + qq*8;
        cpasync16(dst, src, 16);
    }
    #pragma unroll
    for (int c = tid; c < 1024; c += 256) {        // B hi/lo
        int part = c >> 9;
        int r    = (c >> 2) & 127;
        int qq   = c & 3;
        uint32_t dst = base + 2*PB + part*PB + r*80 + qq*16;
        int ok = (n0 + r < N) ? 16 : 0;
        const bf16* src = (part ? Bl : Bh) + (ok ? ((ll)r*ldb + k0 + qq*8) : 0);
        cpasync16(dst, src, ok);
    }
    cp_commit();
}

__global__ void __launch_bounds__(256, 2)
k_gemm(const bf16* __restrict__ Ahi, const bf16* __restrict__ Alo,
       const bf16* __restrict__ A2h, const bf16* __restrict__ A2l, int splitM,
       ll lda, ll aq, ll ar,
       const bf16* __restrict__ Bhi, const bf16* __restrict__ Blo, ll ldb, ll bq, ll br,
       float* __restrict__ Cf, bf16* __restrict__ Chi, bf16* __restrict__ Clo, ll ldc, ll cq, ll cr,
       const float* __restrict__ bias, int N, int K, int ZD, int mode, int skipmode)
{
    extern __shared__ char dsm[];
    const int PB  = 128*80;
    const int STG = 4*PB;          // 40960 bytes per stage

    int m0 = blockIdx.y << 7;
    int n0 = blockIdx.x << 7;

    if (skipmode == 2 && n0 < 769 - m0) return;        // never-read raw BD columns
    if (skipmode == 4 && n0 < 512 && m0 < 4096) return; // q outputs for mem rows: never read
    int nKb = K >> 5;
    if (skipmode == 3) {
        int lim = ((m0 + 1151) >> 5) + 1;              // probs zero beyond j = i_max + MLEN
        if (lim < nKb) nKb = lim;
    }

    uint32_t sb = smem_u32(dsm);
    int tid  = threadIdx.x;
    int wid  = tid >> 5, lane = tid & 31;
    int wm   = wid >> 2;
    int wn   = wid & 3;
    int tg   = lane >> 2, tq = lane & 3;

    int z  = blockIdx.z;
    ll offA = (ll)(z / ZD) * aq + (ll)(z % ZD) * ar;
    ll offB = (ll)(z / ZD) * bq + (ll)(z % ZD) * br;
    ll offC = (ll)(z / ZD) * cq + (ll)(z % ZD) * cr;

    const bf16* Asrc_h = Ahi;
    const bf16* Asrc_l = Alo;
    int mrow = m0;
    if (splitM > 0 && m0 >= splitM) { Asrc_h = A2h; Asrc_l = A2l; mrow = m0 - splitM; }
    const bf16* Ah = Asrc_h + offA + (ll)mrow * lda;
    const bf16* Al = Asrc_l + offA + (ll)mrow * lda;
    const bf16* Bh = Bhi + offB + (ll)n0 * ldb;
    const bf16* Bl = Blo + offB + (ll)n0 * ldb;

    float acc[4][4][4];
    #pragma unroll
    for (int i = 0; i < 4; i++)
        #pragma unroll
        for (int j = 0; j < 4; j++)
            #pragma unroll
            for (int r = 0; r < 4; r++) acc[i][j][r] = 0.f;

    load_stage32(sb, Ah, Al, Bh, Bl, lda, ldb, 0, tid, n0, N);

    for (int kb = 0; kb < nKb; kb++) {
        if (kb + 1 < nKb) {
            load_stage32(sb + ((kb+1)&1)*STG, Ah, Al, Bh, Bl, lda, ldb,
                         (kb+1) << 5, tid, n0, N);
            cp_wait1();
        } else {
            cp_wait0();
        }
        __syncthreads();

        const uint32_t* As = (const uint32_t*)(dsm + (kb&1)*STG);
        const uint32_t* Bs = (const uint32_t*)(dsm + (kb&1)*STG + 2*PB);
        const int AP = PB/4, BP = PB/4;

        #pragma unroll
        for (int kk = 0; kk < 2; kk++) {
            uint32_t a_h[4][4], a_l[4][4], b_h[4][2], b_l[4][2];
            int kw = kk*8 + tq;
            #pragma unroll
            for (int mt = 0; mt < 4; mt++) {
                int r0 = (wm*64 + mt*16 + tg) * 20;
                int r1 = r0 + 8*20;
                a_h[mt][0] = As[r0 + kw];      a_h[mt][1] = As[r1 + kw];
                a_h[mt][2] = As[r0 + kw + 4];  a_h[mt][3] = As[r1 + kw + 4];
                a_l[mt][0] = As[AP + r0 + kw];     a_l[mt][1] = As[AP + r1 + kw];
                a_l[mt][2] = As[AP + r0 + kw + 4]; a_l[mt][3] = As[AP + r1 + kw + 4];
            }
            #pragma unroll
            for (int nt = 0; nt < 4; nt++) {
                int nr = (wn*32 + nt*8 + tg) * 20;
                b_h[nt][0] = Bs[nr + kw];      b_h[nt][1] = Bs[nr + kw + 4];
                b_l[nt][0] = Bs[BP + nr + kw]; b_l[nt][1] = Bs[BP + nr + kw + 4];
            }
            #pragma unroll
            for (int mt = 0; mt < 4; mt++)
                #pragma unroll
                for (int nt = 0; nt < 4; nt++) {
                    mma16816(acc[mt][nt], a_h[mt], b_h[nt]);
                    mma16816(acc[mt][nt], a_h[mt], b_l[nt]);
                    mma16816(acc[mt][nt], a_l[mt], b_h[nt]);
                }
        }
        __syncthreads();
    }

    // epilogue (vectorized: 2 consecutive n per store)
    bool do_bias = (mode & 4) && (blockIdx.z == 0);
    #pragma unroll
    for (int mt = 0; mt < 4; mt++) {
        #pragma unroll
        for (int nt = 0; nt < 4; nt++) {
            int n = n0 + wn*32 + nt*8 + tq*2;
            if (n >= N) continue;
            float b0 = 0.f, b1 = 0.f;
            if (do_bias) { b0 = bias[n]; b1 = bias[n+1]; }
            #pragma unroll
            for (int half = 0; half < 2; half++) {
                int m = m0 + wm*64 + mt*16 + tg + half*8;
                float v0 = acc[mt][nt][half*2]     + b0;
                float v1 = acc[mt][nt][half*2 + 1] + b1;
                if (mode & 8) { v0 = fmaxf(v0, 0.f); v1 = fmaxf(v1, 0.f); }
                if (skipmode == 2) {
                    int j = n - 1023 + m;       // pre-shifted column
                    float* row = Cf + offC + (ll)m * ldc;
                    if (j >= 0)     row[j]     = v0;
                    if (j + 1 >= 0) row[j + 1] = v1;
                    continue;
                }
                ll cidx = offC + (ll)m * ldc + n;
                if (mode & 1) *(float2*)(Cf + cidx) = make_float2(v0, v1);
                if (mode & 2) {
                    uint32_t hi, lo;
                    pack_split(v0, v1, hi, lo);
                    *(uint32_t*)(Chi + cidx) = hi;
                    *(uint32_t*)(Clo + cidx) = lo;
                }
            }
        }
    }
}

// ================= fused flash attention =================
__device__ __forceinline__ void flash_load_kv(uint32_t base,
        const bf16* __restrict__ Kh, const bf16* __restrict__ Kl,
        const bf16* __restrict__ Vh, const bf16* __restrict__ Vl,
        int j0, int tid)
{
    #pragma unroll
    for (int c = tid; c < 2048; c += 256) {
        int t4 = c >> 9;           // 0 Kh, 1 Kl, 2 Vh, 3 Vl
        int r  = (c >> 3) & 63;
        int qq = c & 7;
        uint32_t dst = base + t4*9216 + r*144 + qq*16;
        const bf16* src;
        if (t4 == 0)      src = Kh + (ll)(j0 + r)*6144 + qq*8;
        else if (t4 == 1) src = Kl + (ll)(j0 + r)*6144 + qq*8;
        else if (t4 == 2) src = Vh + (ll)r*2048 + j0 + qq*8;
        else              src = Vl + (ll)r*2048 + j0 + qq*8;
        cpasync16(dst, src, 16);
    }
    cp_commit();
}

__global__ void __launch_bounds__(256, 1)
k_flash(const bf16* __restrict__ qh_, const bf16* __restrict__ ql_,
        const bf16* __restrict__ kh_, const bf16* __restrict__ kl_,
        const bf16* __restrict__ vh_, const bf16* __restrict__ vl_,
        const float* __restrict__ bd_,
        bf16* __restrict__ voh, bf16* __restrict__ vol)
{
    extern __shared__ char sm[];
    const int QLO = 0, QLL = 18432, ST0 = 36864, STSZ = 36864;

    int tid = threadIdx.x, wid = tid >> 5, lane = tid & 31;
    int tg = lane >> 2, tq = lane & 3;
    int i0 = (7 - (int)blockIdx.x) << 7;   // heavy causal blocks scheduled first
    int z  = blockIdx.y;
    int b = z >> 3, h_ = z & 7;
    uint32_t sb = smem_u32(sm);

    const bf16* Qh = qh_ + (ll)z*65536 + (ll)i0*64;
    const bf16* Ql = ql_ + (ll)z*65536 + (ll)i0*64;
    const bf16* Kh = kh_ + (ll)b*1536 + h_*64;
    const bf16* Kl = kl_ + (ll)b*1536 + h_*64;
    const bf16* Vh = vh_ + (ll)z*131072;
    const bf16* Vl = vl_ + (ll)z*131072;
    const float* BD = bd_ + (ll)z*2097152;

    #pragma unroll
    for (int c = tid; c < 2048; c += 256) {
        int part = c >> 10, r = (c >> 3) & 127, qq = c & 7;
        cpasync16(sb + (part ? QLL : QLO) + r*144 + qq*16,
                  (part ? Ql : Qh) + (ll)r*64 + qq*8, 16);
    }
    cp_commit();

    int jbmax = ((i0 + 127 + MLEN) >> 6) + 1;
    if (jbmax > 32) jbmax = 32;
    flash_load_kv(sb + ST0, Kh, Kl, Vh, Vl, 0, tid);

    float O[8][4];
    #pragma unroll
    for (int dt = 0; dt < 8; dt++) { O[dt][0]=O[dt][1]=O[dt][2]=O[dt][3]=0.f; }
    float mA = -1e30f, mB = -1e30f, lA = 0.f, lB = 0.f;
    int riA = i0 + wid*16 + tg, riB = riA + 8;

    const uint32_t* Qsh = (const uint32_t*)(sm + QLO);
    const uint32_t* Qsl = (const uint32_t*)(sm + QLL);
    const float* BDrA = BD + (ll)riA*2048;
    const float* BDrB = BD + (ll)riB*2048;

    for (int jb = 0; jb < jbmax; jb++) {
        int s = jb & 1;
        if (jb + 1 < jbmax) {
            flash_load_kv(sb + ST0 + (s^1)*STSZ, Kh, Kl, Vh, Vl, (jb+1) << 6, tid);
            cp_wait1();
        } else {
            cp_wait0();
        }
        __syncthreads();

        const uint32_t* Ksh = (const uint32_t*)(sm + ST0 + s*STSZ);
        const uint32_t* Ksl = Ksh + 2304;
        const uint32_t* Vsh = Ksh + 4608;
        const uint32_t* Vsl = Ksh + 6912;
        int j0 = jb << 6;

        float S[8][4];
        #pragma unroll
        for (int nt = 0; nt < 8; nt++) { S[nt][0]=S[nt][1]=S[nt][2]=S[nt][3]=0.f; }

        #pragma unroll
        for (int kt = 0; kt < 4; kt++) {
            int kw = kt*8 + tq;
            int r0 = (wid*16 + tg) * 36, r1 = r0 + 8*36;
            uint32_t ah[4], al[4];
            ah[0]=Qsh[r0+kw]; ah[1]=Qsh[r1+kw]; ah[2]=Qsh[r0+kw+4]; ah[3]=Qsh[r1+kw+4];
            al[0]=Qsl[r0+kw]; al[1]=Qsl[r1+kw]; al[2]=Qsl[r0+kw+4]; al[3]=Qsl[r1+kw+4];
            #pragma unroll
            for (int nt = 0; nt < 8; nt++) {
                int nr = (nt*8 + tg) * 36;
                uint32_t bh2[2], bl2[2];
                bh2[0]=Ksh[nr+kw]; bh2[1]=Ksh[nr+kw+4];
                bl2[0]=Ksl[nr+kw]; bl2[1]=Ksl[nr+kw+4];
                mma16816(S[nt], ah, bh2);
                mma16816(S[nt], ah, bl2);
                mma16816(S[nt], al, bh2);
            }
        }

        float bmA = -1e30f, bmB = -1e30f;
        #pragma unroll
        for (int nt = 0; nt < 8; nt++) {
            int j = j0 + nt*8 + 2*tq;
            float2 bA = *(const float2*)(BDrA + j);
            float2 bB = *(const float2*)(BDrB + j);
            S[nt][0] = (j     <= riA + MLEN) ? (S[nt][0] + bA.x)*0.125f : -1e30f;
            S[nt][1] = (j + 1 <= riA + MLEN) ? (S[nt][1] + bA.y)*0.125f : -1e30f;
            S[nt][2] = (j     <= riB + MLEN) ? (S[nt][2] + bB.x)*0.125f : -1e30f;
            S[nt][3] = (j + 1 <= riB + MLEN) ? (S[nt][3] + bB.y)*0.125f : -1e30f;
            bmA = fmaxf(bmA, fmaxf(S[nt][0], S[nt][1]));
            bmB = fmaxf(bmB, fmaxf(S[nt][2], S[nt][3]));
        }
        bmA = fmaxf(bmA, __shfl_xor_sync(0xffffffffu, bmA, 1));
        bmA = fmaxf(bmA, __shfl_xor_sync(0xffffffffu, bmA, 2));
        bmB = fmaxf(bmB, __shfl_xor_sync(0xffffffffu, bmB, 1));
        bmB = fmaxf(bmB, __shfl_xor_sync(0xffffffffu, bmB, 2));
        float mAn = fmaxf(mA, bmA), mBn = fmaxf(mB, bmB);
        float aAs = __expf(mA - mAn), aBs = __expf(mB - mBn);

        float sA = 0.f, sB = 0.f;
        #pragma unroll
        for (int nt = 0; nt < 8; nt++) {
            S[nt][0] = __expf(S[nt][0] - mAn);
            S[nt][1] = __expf(S[nt][1] - mAn);
            S[nt][2] = __expf(S[nt][2] - mBn);
            S[nt][3] = __expf(S[nt][3] - mBn);
            sA += S[nt][0] + S[nt][1];
            sB += S[nt][2] + S[nt][3];
            O[nt][0] *= aAs; O[nt][1] *= aAs; O[nt][2] *= aBs; O[nt][3] *= aBs;
        }
        sA += __shfl_xor_sync(0xffffffffu, sA, 1);
        sA += __shfl_xor_sync(0xffffffffu, sA, 2);
        sB += __shfl_xor_sync(0xffffffffu, sB, 1);
        sB += __shfl_xor_sync(0xffffffffu, sB, 2);
        lA = lA*aAs + sA; lB = lB*aBs + sB;
        mA = mAn; mB = mBn;

        #pragma unroll
        for (int kt = 0; kt < 4; kt++) {
            uint32_t pah[4], pal[4];
            pack_split(S[2*kt][0],   S[2*kt][1],   pah[0], pal[0]);
            pack_split(S[2*kt][2],   S[2*kt][3],   pah[1], pal[1]);
            pack_split(S[2*kt+1][0], S[2*kt+1][1], pah[2], pal[2]);
            pack_split(S[2*kt+1][2], S[2*kt+1][3], pah[3], pal[3]);
            int kw = kt*8 + tq;
            #pragma unroll
            for (int dt = 0; dt < 8; dt++) {
                int nr = (dt*8 + tg) * 36;
                uint32_t bh2[2], bl2[2];
                bh2[0]=Vsh[nr+kw]; bh2[1]=Vsh[nr+kw+4];
                bl2[0]=Vsl[nr+kw]; bl2[1]=Vsl[nr+kw+4];
                mma16816(O[dt], pah, bh2);
                mma16816(O[dt], pah, bl2);
                mma16816(O[dt], pal, bh2);
            }
        }
        __syncthreads();
    }

    float ivA = 1.f/lA, ivB = 1.f/lB;
    #pragma unroll
    for (int dt = 0; dt < 8; dt++) {
        int d0 = dt*8 + 2*tq;
        ll aA = (ll)riA*2048 + b*512 + h_*64 + d0;
        ll aB = (ll)riB*2048 + b*512 + h_*64 + d0;
        uint32_t hi, lo;
        pack_split(O[dt][0]*ivA, O[dt][1]*ivA, hi, lo);
        *(uint32_t*)(voh + aA) = hi; *(uint32_t*)(vol + aA) = lo;
        pack_split(O[dt][2]*ivB, O[dt][3]*ivB, hi, lo);
        *(uint32_t*)(voh + aB) = hi; *(uint32_t*)(vol + aB) = lo;
    }
}

// ================= elementwise / small kernels =================
__global__ void k_split(const float4* __restrict__ in, uint2* __restrict__ hi,
                        uint2* __restrict__ lo, ll n4){
    ll i = (ll)blockIdx.x * blockDim.x + threadIdx.x;
    if (i >= n4) return;
    float4 v = in[i];
    uint32_t h0,l0,h1,l1;
    pack_split(v.x, v.y, h0, l0);
    pack_split(v.z, v.w, h1, l1);
    hi[i] = make_uint2(h0, h1);
    lo[i] = make_uint2(l0, l1);
}

__global__ void k_embed(const int* __restrict__ x, const float* __restrict__ emb,
                        float* __restrict__ h, bf16* __restrict__ hh, bf16* __restrict__ hl)
{
    int idx = blockIdx.x * blockDim.x + threadIdx.x;
    if (idx >= QLEN*BSZ*DM) return;
    int d = idx & (DM-1);
    int b = (idx >> 9) & 3;
    int i = idx >> 11;
    int tok = x[i*BSZ + b];
    float v = emb[(ll)tok*DM + d] * 22.627416997969522f;
    h[idx] = v;
    split2(v, hh + idx, hl + idx);
}

__global__ void k_posemb(bf16* __restrict__ rh, bf16* __restrict__ rl)
{
    int idx = blockIdx.x * blockDim.x + threadIdx.x;
    if (idx >= KLEN*DM) return;
    int d = idx & (DM-1);
    int k = idx >> 9;
    double pos = (double)(KLEN - 1 - k);
    int t = (d < 256) ? d : d - 256;
    double f = exp(-(double)t * (log(10000.0) / 256.0));
    double a = pos * f;
    float v = (float)((d < 256) ? sin(a) : cos(a));
    split2(v, rh + idx, rl + idx);
}

// q + biases, re-split into [bh][i][64]
__global__ void k_qbias(const bf16* __restrict__ hh, const bf16* __restrict__ hl,
                        const float* __restrict__ rwb, const float* __restrict__ rrb,
                        bf16* __restrict__ qwh, bf16* __restrict__ qwl,
                        bf16* __restrict__ qrh, bf16* __restrict__ qrl)
{
    int idx = blockIdx.x * blockDim.x + threadIdx.x;
    if (idx >= 32*1024*64) return;
    int d = idx & 63;
    int i = (idx >> 6) & 1023;
    int z = idx >> 16;
    int b = z >> 3, h_ = z & 7;
    ll src = ((ll)(MLEN + i)*BSZ + b)*QKV + h_*64 + d;
    float q = __bfloat162float(hh[src]) + __bfloat162float(hl[src]);
    split2(q + rwb[h_*64 + d], qwh + idx, qwl + idx);
    split2(q + rrb[h_*64 + d], qrh + idx, qrl + idx);
}

__global__ void k_vtrans(const bf16* __restrict__ hh, const bf16* __restrict__ hl,
                         bf16* __restrict__ vth, bf16* __restrict__ vtl)
{
    __shared__ bf16 th[64][65], tl[64][65];
    int z = blockIdx.y;
    int j0 = blockIdx.x << 6;
    int b = z >> 3, h_ = z & 7;
    #pragma unroll
    for (int p = 0; p < 16; p++) {
        int jj = (threadIdx.x >> 6) + p*4;
        int d  = threadIdx.x & 63;
        ll src = ((ll)(j0 + jj)*BSZ + b)*QKV + 1024 + h_*64 + d;
        th[jj][d] = hh[src];
        tl[jj][d] = hl[src];
    }
    __syncthreads();
    #pragma unroll
    for (int p = 0; p < 16; p++) {
        int dd = (threadIdx.x >> 6) + p*4;
        int j  = threadIdx.x & 63;
        ll dst = (ll)z*131072 + (ll)dd*2048 + j0 + j;
        vth[dst] = th[j][dd];
        vtl[dst] = tl[j][dd];
    }
}

// h = LN(h + res + res2)  — two split-K partial residuals
__global__ void __launch_bounds__(256)
k_add_ln(float* __restrict__ h, const float* __restrict__ res, const float* __restrict__ res2,
         const float* __restrict__ g, const float* __restrict__ be,
         bf16* __restrict__ hh, bf16* __restrict__ hl)
{
    int row = blockIdx.x;
    int tid = threadIdx.x;
    int lane = tid & 31, wid = tid >> 5;
    __shared__ float red[8];
    __shared__ float s_mean, s_rstd;

    float* hp = h + (ll)row*DM;
    const float* rp  = res  + (ll)row*DM;
    const float* rp2 = res2 + (ll)row*DM;

    float v0 = hp[tid]       + rp[tid]       + rp2[tid];
    float v1 = hp[tid + 256] + rp[tid + 256] + rp2[tid + 256];

    float s = v0 + v1;
    #pragma unroll
    for (int o = 16; o > 0; o >>= 1) s += __shfl_xor_sync(0xffffffffu, s, o);
    if (lane == 0) red[wid] = s;
    __syncthreads();
    if (wid == 0) {
        float t = (lane < 8) ? red[lane] : 0.f;
        #pragma unroll
        for (int o = 4; o > 0; o >>= 1) t += __shfl_xor_sync(0xffffffffu, t, o);
        if (lane == 0) s_mean = t * (1.0f/512.0f);
    }
    __syncthreads();
    float mean = s_mean;
    float d0 = v0 - mean, d1 = v1 - mean;

    s = d0*d0 + d1*d1;
    #pragma unroll
    for (int o = 16; o > 0; o >>= 1) s += __shfl_xor_sync(0xffffffffu, s, o);
    if (lane == 0) red[wid] = s;
    __syncthreads();
    if (wid == 0) {
        float t = (lane < 8) ? red[lane] : 0.f;
        #pragma unroll
        for (int o = 4; o > 0; o >>= 1) t += __shfl_xor_sync(0xffffffffu, t, o);
        if (lane == 0) s_rstd = rsqrtf(t * (1.0f/512.0f) + 1e-5f);
    }
    __syncthreads();
    float rs = s_rstd;

    float o0 = d0 * rs * g[tid]       + be[tid];
    float o1 = d1 * rs * g[tid + 256] + be[tid + 256];
    hp[tid]       = o0;
    hp[tid + 256] = o1;
    ll base = (ll)row*DM;
    split2(o0, hh + base + tid,       hl + base + tid);
    split2(o1, hh + base + tid + 256, hl + base + tid + 256);
}

// ================= host =================
static const int SMGEMM = 2*4*128*80;      // 81920
static const int SMFLSH = 36864 + 2*36864; // 110592

extern "C" void kernel_launch(void* const* d_in, const int* in_sizes, int n_in,
                              void* d_out, int out_size)
{
    const int*   x        = (const int*)  d_in[0];
    const float* mems     = (const float*)d_in[1];
    const float* emb      = (const float*)d_in[2];
    const float* qkv_w    = (const float*)d_in[3];
    const float* r_net_w  = (const float*)d_in[4];
    const float* o_w      = (const float*)d_in[5];
    const float* ln1_g    = (const float*)d_in[6];
    const float* ln1_b    = (const float*)d_in[7];
    const float* ff_w1    = (const float*)d_in[8];
    const float* ff_b1    = (const float*)d_in[9];
    const float* ff_w2    = (const float*)d_in[10];
    const float* ff_b2    = (const float*)d_in[11];
    const float* ln2_g    = (const float*)d_in[12];
    const float* ln2_b    = (const float*)d_in[13];
    const float* r_w_bias = (const float*)d_in[14];
    const float* r_r_bias = (const float*)d_in[15];
    const float* proj_w   = (const float*)d_in[16];
    const float* proj_b   = (const float*)d_in[17];
    float* out = (float*)d_out;

    static bool attr_done = false;
    if (!attr_done) {
        cudaFuncSetAttribute(k_gemm,  cudaFuncAttributeMaxDynamicSharedMemorySize, SMGEMM);
        cudaFuncSetAttribute(k_flash, cudaFuncAttributeMaxDynamicSharedMemorySize, SMFLSH);
        attr_done = true;
    }

    bf16 *qkvwh,*qkvwl,*rnwh,*rnwl,*owh,*owl,*f1h,*f1l,*f2h,*f2l,*pwh,*pwl,*memh,*meml;
    bf16 *hdh,*hdl,*rh,*rl,*rkh,*rkl,*qwh,*qwl,*qrh,*qrl;
    bf16 *vth,*vtl,*vech,*vecl,*hh,*hl,*ffh,*ffl;
    float *bd,*h,*tmp;
    cudaGetSymbolAddress((void**)&qkvwh, g_qkvwh); cudaGetSymbolAddress((void**)&qkvwl, g_qkvwl);
    cudaGetSymbolAddress((void**)&rnwh,  g_rnwh);  cudaGetSymbolAddress((void**)&rnwl,  g_rnwl);
    cudaGetSymbolAddress((void**)&owh,   g_owh);   cudaGetSymbolAddress((void**)&owl,   g_owl);
    cudaGetSymbolAddress((void**)&f1h,   g_f1h);   cudaGetSymbolAddress((void**)&f1l,   g_f1l);
    cudaGetSymbolAddress((void**)&f2h,   g_f2h);   cudaGetSymbolAddress((void**)&f2l,   g_f2l);
    cudaGetSymbolAddress((void**)&pwh,   g_pwh);   cudaGetSymbolAddress((void**)&pwl,   g_pwl);
    cudaGetSymbolAddress((void**)&memh,  g_memh);  cudaGetSymbolAddress((void**)&meml,  g_meml);
    cudaGetSymbolAddress((void**)&hdh,   g_hdh);   cudaGetSymbolAddress((void**)&hdl,   g_hdl);
    cudaGetSymbolAddress((void**)&rh,    g_rh);    cudaGetSymbolAddress((void**)&rl,    g_rl);
    cudaGetSymbolAddress((void**)&rkh,   g_rkh);   cudaGetSymbolAddress((void**)&rkl,   g_rkl);
    cudaGetSymbolAddress((void**)&qwh,   g_qwh);   cudaGetSymbolAddress((void**)&qwl,   g_qwl);
    cudaGetSymbolAddress((void**)&qrh,   g_qrh);   cudaGetSymbolAddress((void**)&qrl,   g_qrl);
    cudaGetSymbolAddress((void**)&vth,   g_vth);   cudaGetSymbolAddress((void**)&vtl,   g_vtl);
    cudaGetSymbolAddress((void**)&vech,  g_vech);  cudaGetSymbolAddress((void**)&vecl,  g_vecl);
    cudaGetSymbolAddress((void**)&hh,    g_hh);    cudaGetSymbolAddress((void**)&hl,    g_hl);
    cudaGetSymbolAddress((void**)&ffh,   g_ffh);   cudaGetSymbolAddress((void**)&ffl,   g_ffl);
    cudaGetSymbolAddress((void**)&bd,    g_bd);
    cudaGetSymbolAddress((void**)&h,     g_h);     cudaGetSymbolAddress((void**)&tmp,   g_tmp);
    float* tmp2 = tmp + 2097152;

    const int NTOK = QLEN*BSZ;

    k_split<<<(2359296 +255)/256, 256>>>((const float4*)qkv_w, (uint2*)qkvwh, (uint2*)qkvwl, 2359296LL);
    k_embed <<<(QLEN*BSZ*DM + 255)/256, 256>>>(x, emb, h, hh, hl);
    k_split<<<(6291456 +255)/256, 256>>>((const float4*)mems, (uint2*)memh, (uint2*)meml, 6291456LL);

    // #4 (ncu capture slot): layer-0 QKV GEMM
    k_gemm<<<dim3(12, 64, 1), 256, SMGEMM>>>(
        memh, meml, hh, hl, 4096,
        512, 0, 0,
        qkvwh, qkvwl, 512, 0, 0,
        nullptr, hdh, hdl, 1536, 0, 0,
        nullptr, 1536, 512, 1, 2, 4);

    k_posemb<<<(KLEN*DM + 255)/256, 256>>>(rh, rl);
    k_split<<<(786432  +255)/256, 256>>>((const float4*)r_net_w, (uint2*)rnwh, (uint2*)rnwl, 786432LL);

    // ALL-layer rhk in ONE batched GEMM: rk[l] = r x r_net_w[l]^T  (z = layer)
    k_gemm<<<dim3(4, 16, 12), 256, SMGEMM>>>(
        rh, rl, nullptr, nullptr, 0,
        512, 0, 0,
        rnwh, rnwl, 512, 262144, 0,
        nullptr, rkh, rkl, 512, 1048576, 0,
        nullptr, 512, 512, 1, 2, 0);

    k_split<<<(786432  +255)/256, 256>>>((const float4*)o_w,    (uint2*)owh, (uint2*)owl, 786432LL);
    k_split<<<(3145728 +255)/256, 256>>>((const float4*)ff_w1,  (uint2*)f1h, (uint2*)f1l, 3145728LL);
    k_split<<<(3145728 +255)/256, 256>>>((const float4*)ff_w2,  (uint2*)f2h, (uint2*)f2l, 3145728LL);
    k_split<<<(1280000 +255)/256, 256>>>((const float4*)proj_w, (uint2*)pwh, (uint2*)pwl, 1280000LL);

    for (int l = 0; l < NL; l++) {
        if (l > 0) {
            k_gemm<<<dim3(12, 64, 1), 256, SMGEMM>>>(
                memh + (ll)l*2097152, meml + (ll)l*2097152, hh, hl, 4096,
                512, 0, 0,
                qkvwh + (ll)l*786432, qkvwl + (ll)l*786432, 512, 0, 0,
                nullptr, hdh, hdl, 1536, 0, 0,
                nullptr, 1536, 512, 1, 2, 4);
        }

        // q + biases
        k_qbias<<<(32*1024*64 + 255)/256, 256>>>(hdh, hdl, r_w_bias, r_r_bias, qwh, qwl, qrh, qrl);

        // BD raw -> PRE-SHIFTED store (skipmode 2); rhk from batched buffer
        k_gemm<<<dim3(16, 8, 32), 256, SMGEMM>>>(
            qrh, qrl, nullptr, nullptr, 0,
            64, 8LL*65536, 65536,
            rkh + (ll)l*1048576, rkl + (ll)l*1048576, 512, 0, 64,
            bd, nullptr, nullptr, 2048, 8LL*2097152, 2097152,
            nullptr, 2048, 64, 8, 1, 2);

        // V transpose
        k_vtrans<<<dim3(32, 32), 256>>>(hdh, hdl, vth, vtl);

        // fused AC + BDshift + mask + softmax + PV (heavy-first CTA order)
        k_flash<<<dim3(8, 32), 256, SMFLSH>>>(
            qwh, qwl, hdh + 512, hdl + 512, vth, vtl, bd, vech, vecl);

        // attn_out = vec x o_w^T  — SPLIT-K x2: z selects K-half + output buffer
        k_gemm<<<dim3(4, 32, 2), 256, SMGEMM>>>(
            vech, vecl, nullptr, nullptr, 0,
            512, 256, 0,
            owh + (ll)l*262144, owl + (ll)l*262144, 512, 256, 0,
            tmp, nullptr, nullptr, 512, 2097152, 0,
            nullptr, 512, 256, 1, 1, 0);

        k_add_ln<<<NTOK, 256>>>(h, tmp, tmp2, ln1_g + l*DM, ln1_b + l*DM, hh, hl);

        // ff = relu(h x ff_w1^T + b1)
        k_gemm<<<dim3(16, 32, 1), 256, SMGEMM>>>(
            hh, hl, nullptr, nullptr, 0,
            512, 0, 0,
            f1h + (ll)l*1048576, f1l + (ll)l*1048576, 512, 0, 0,
            nullptr, ffh, ffl, 2048, 0, 0,
            ff_b1 + (ll)l*DI, 2048, 512, 1, 2|4|8, 0);

        // tmp = ff x ff_w2^T + b2  — SPLIT-K x2 (bias applied by z=0 only)
        k_gemm<<<dim3(4, 32, 2), 256, SMGEMM>>>(
            ffh, ffl, nullptr, nullptr, 0,
            2048, 1024, 0,
            f2h + (ll)l*1048576, f2l + (ll)l*1048576, 2048, 1024, 0,
            tmp, nullptr, nullptr, 512, 2097152, 0,
            ff_b2 + (ll)l*DM, 512, 1024, 1, 1|4, 0);

        k_add_ln<<<NTOK, 256>>>(h, tmp, tmp2, ln2_g + l*DM, ln2_b + l*DM, hh, hl);
    }

    // logits = h x proj_w^T + proj_b
    k_gemm<<<dim3(79, 32, 1), 256, SMGEMM>>>(
        hh, hl, nullptr, nullptr, 0,
        512, 0, 0,
        pwh, pwl, 512, 0, 0,
        out, nullptr, nullptr, 10000, 0, 0,
        proj_b, 10000, 512, 1, 1|4, 0);
}

// round 17
// speedup vs baseline: 1.0593x; 1.0242x over previous
#include <cuda_runtime.h>
#include <cuda_bf16.h>
#include <math.h>
#include <stdint.h>

#define QLEN 1024
#define MLEN 1024
#define KLEN 2048
#define BSZ  4
#define NL   12
#define NH   8
#define DHD  64
#define DM   512
#define DI   2048
#define NV   10000
#define HD   512
#define QKV  1536

typedef __nv_bfloat16 bf16;
typedef long long ll;

// ---------------- scratch (device globals; no allocations) ----------------
__device__ bf16 g_qkvwh[9437184], g_qkvwl[9437184];
__device__ bf16 g_rnwh[3145728],  g_rnwl[3145728];
__device__ bf16 g_owh[3145728],   g_owl[3145728];
__device__ bf16 g_f1h[12582912],  g_f1l[12582912];
__device__ bf16 g_f2h[12582912],  g_f2l[12582912];
__device__ bf16 g_pwh[5120000],   g_pwl[5120000];
__device__ bf16 g_memh[25165824], g_meml[25165824];   // all-layer split mems

__device__ bf16 g_hdh[12582912],  g_hdl[12582912];
__device__ bf16 g_rh[1048576],    g_rl[1048576];
__device__ bf16 g_rkh[12582912],  g_rkl[12582912];    // ALL-layer r_head_k (batched)
__device__ bf16 g_qwh[2097152],   g_qwl[2097152];
__device__ bf16 g_qrh[2097152],   g_qrl[2097152];
__device__ float g_bd[67108864];          // pre-shifted BD: [bh][i][j]
__device__ bf16 g_vth[4194304],   g_vtl[4194304];
__device__ bf16 g_vech[2097152],  g_vecl[2097152];
__device__ float g_h[2097152],    g_tmp[4194304];     // 2 split-K partial buffers
__device__ bf16 g_hh[2097152],    g_hl[2097152];
__device__ bf16 g_ffh[8388608],   g_ffl[8388608];

// ---------------- helpers ----------------
__device__ __forceinline__ uint32_t smem_u32(const void* p){
    uint32_t a;
    asm("{ .reg .u64 t; cvta.to.shared.u64 t, %1; cvt.u32.u64 %0, t; }" : "=r"(a) : "l"(p));
    return a;
}
__device__ __forceinline__ void cpasync16(uint32_t dst, const void* src, int sz){
    asm volatile("cp.async.cg.shared.global [%0], [%1], 16, %2;"
                 :: "r"(dst), "l"(src), "r"(sz) : "memory");
}
__device__ __forceinline__ void cp_commit(){
    asm volatile("cp.async.commit_group;" ::: "memory");
}
__device__ __forceinline__ void cp_wait0(){
    asm volatile("cp.async.wait_group 0;" ::: "memory");
}
__device__ __forceinline__ void cp_wait1(){
    asm volatile("cp.async.wait_group 1;" ::: "memory");
}
__device__ __forceinline__ void mma16816(float* c, const uint32_t* a, const uint32_t* b){
    asm volatile(
        "mma.sync.aligned.m16n8k16.row.col.f32.bf16.bf16.f32 "
        "{%0,%1,%2,%3}, {%4,%5,%6,%7}, {%8,%9}, {%0,%1,%2,%3};"
        : "+f"(c[0]), "+f"(c[1]), "+f"(c[2]), "+f"(c[3])
        : "r"(a[0]), "r"(a[1]), "r"(a[2]), "r"(a[3]), "r"(b[0]), "r"(b[1]));
}
__device__ __forceinline__ void split2(float v, bf16* hi, bf16* lo){
    bf16 h = __float2bfloat16(v);
    *hi = h;
    *lo = __float2bfloat16(v - __bfloat162float(h));
}
__device__ __forceinline__ void pack_split(float x, float y, uint32_t& hi, uint32_t& lo){
    bf16 hx = __float2bfloat16(x), hy = __float2bfloat16(y);
    hi = (uint32_t)__bfloat16_as_ushort(hx) | ((uint32_t)__bfloat16_as_ushort(hy) << 16);
    bf16 lx = __float2bfloat16(x - __bfloat162float(hx));
    bf16 ly = __float2bfloat16(y - __bfloat162float(hy));
    lo = (uint32_t)__bfloat16_as_ushort(lx) | ((uint32_t)__bfloat16_as_ushort(ly) << 16);
}

// ================= split-bf16 mma.sync GEMM (128x128 tile, BK=32, 2 CTAs/SM) =================
// FROZEN r12/r14 engine. C[m,n] = sum_k A[m,k]*B[n,k]; (hi,lo) pairs, 3-term compensation.
// Split-K usage: ZD=1, aq=bq=K/2 (element offset into the K window), cq = output buffer stride.
// Bias is applied only by blockIdx.z == 0.
// mode bits: 1=fp32 Cf, 2=split Chi/Clo, 4=+bias, 8=relu
// skipmode: 0 none; 2 BD pre-shift store + unread-col skip; 3 PV K clamp; 4 QKV q-tile skip
__device__ __forceinline__ void load_stage32(uint32_t base,
        const bf16* __restrict__ Ah, const bf16* __restrict__ Al,
        const bf16* __restrict__ Bh, const bf16* __restrict__ Bl,
        ll lda, ll ldb, int k0, int tid, int n0, int N)
{
    const int PB = 128*80;   // bytes per matrix part
    #pragma unroll
    for (int c = tid; c < 1024; c += 256) {        // A hi/lo
        int part = c >> 9;
        int r    = (c >> 2) & 127;
        int qq   = c & 3;
        uint32_t dst = base + part*PB + r*80 + qq*16;
        const bf16* src = (part ? Al : Ah) + (ll)r*lda + k0 + qq*8;
        cpasync16(dst, src, 16);
    }
    #pragma unroll
    for (int c = tid; c < 1024; c += 256) {        // B hi/lo
        int part = c >> 9;
        int r    = (c >> 2) & 127;
        int qq   = c & 3;
        uint32_t dst = base + 2*PB + part*PB + r*80 + qq*16;
        int ok = (n0 + r < N) ? 16 : 0;
        const bf16* src = (part ? Bl : Bh) + (ok ? ((ll)r*ldb + k0 + qq*8) : 0);
        cpasync16(dst, src, ok);
    }
    cp_commit();
}

__global__ void __launch_bounds__(256, 2)
k_gemm(const bf16* __restrict__ Ahi, const bf16* __restrict__ Alo,
       const bf16* __restrict__ A2h, const bf16* __restrict__ A2l, int splitM,
       ll lda, ll aq, ll ar,
       const bf16* __restrict__ Bhi, const bf16* __restrict__ Blo, ll ldb, ll bq, ll br,
       float* __restrict__ Cf, bf16* __restrict__ Chi, bf16* __restrict__ Clo, ll ldc, ll cq, ll cr,
       const float* __restrict__ bias, int N, int K, int ZD, int mode, int skipmode)
{
    extern __shared__ char dsm[];
    const int PB  = 128*80;
    const int STG = 4*PB;          // 40960 bytes per stage

    int m0 = blockIdx.y << 7;
    int n0 = blockIdx.x << 7;

    if (skipmode == 2 && n0 < 769 - m0) return;        // never-read raw BD columns
    if (skipmode == 4 && n0 < 512 && m0 < 4096) return; // q outputs for mem rows: never read
    int nKb = K >> 5;
    if (skipmode == 3) {
        int lim = ((m0 + 1151) >> 5) + 1;              // probs zero beyond j = i_max + MLEN
        if (lim < nKb) nKb = lim;
    }

    uint32_t sb = smem_u32(dsm);
    int tid  = threadIdx.x;
    int wid  = tid >> 5, lane = tid & 31;
    int wm   = wid >> 2;
    int wn   = wid & 3;
    int tg   = lane >> 2, tq = lane & 3;

    int z  = blockIdx.z;
    ll offA = (ll)(z / ZD) * aq + (ll)(z % ZD) * ar;
    ll offB = (ll)(z / ZD) * bq + (ll)(z % ZD) * br;
    ll offC = (ll)(z / ZD) * cq + (ll)(z % ZD) * cr;

    const bf16* Asrc_h = Ahi;
    const bf16* Asrc_l = Alo;
    int mrow = m0;
    if (splitM > 0 && m0 >= splitM) { Asrc_h = A2h; Asrc_l = A2l; mrow = m0 - splitM; }
    const bf16* Ah = Asrc_h + offA + (ll)mrow * lda;
    const bf16* Al = Asrc_l + offA + (ll)mrow * lda;
    const bf16* Bh = Bhi + offB + (ll)n0 * ldb;
    const bf16* Bl = Blo + offB + (ll)n0 * ldb;

    float acc[4][4][4];
    #pragma unroll
    for (int i = 0; i < 4; i++)
        #pragma unroll
        for (int j = 0; j < 4; j++)
            #pragma unroll
            for (int r = 0; r < 4; r++) acc[i][j][r] = 0.f;

    load_stage32(sb, Ah, Al, Bh, Bl, lda, ldb, 0, tid, n0, N);

    for (int kb = 0; kb < nKb; kb++) {
        if (kb + 1 < nKb) {
            load_stage32(sb + ((kb+1)&1)*STG, Ah, Al, Bh, Bl, lda, ldb,
                         (kb+1) << 5, tid, n0, N);
            cp_wait1();
        } else {
            cp_wait0();
        }
        __syncthreads();

        const uint32_t* As = (const uint32_t*)(dsm + (kb&1)*STG);
        const uint32_t* Bs = (const uint32_t*)(dsm + (kb&1)*STG + 2*PB);
        const int AP = PB/4, BP = PB/4;

        #pragma unroll
        for (int kk = 0; kk < 2; kk++) {
            uint32_t a_h[4][4], a_l[4][4], b_h[4][2], b_l[4][2];
            int kw = kk*8 + tq;
            #pragma unroll
            for (int mt = 0; mt < 4; mt++) {
                int r0 = (wm*64 + mt*16 + tg) * 20;
                int r1 = r0 + 8*20;
                a_h[mt][0] = As[r0 + kw];      a_h[mt][1] = As[r1 + kw];
                a_h[mt][2] = As[r0 + kw + 4];  a_h[mt][3] = As[r1 + kw + 4];
                a_l[mt][0] = As[AP + r0 + kw];     a_l[mt][1] = As[AP + r1 + kw];
                a_l[mt][2] = As[AP + r0 + kw + 4]; a_l[mt][3] = As[AP + r1 + kw + 4];
            }
            #pragma unroll
            for (int nt = 0; nt < 4; nt++) {
                int nr = (wn*32 + nt*8 + tg) * 20;
                b_h[nt][0] = Bs[nr + kw];      b_h[nt][1] = Bs[nr + kw + 4];
                b_l[nt][0] = Bs[BP + nr + kw]; b_l[nt][1] = Bs[BP + nr + kw + 4];
            }
            #pragma unroll
            for (int mt = 0; mt < 4; mt++)
                #pragma unroll
                for (int nt = 0; nt < 4; nt++) {
                    mma16816(acc[mt][nt], a_h[mt], b_h[nt]);
                    mma16816(acc[mt][nt], a_h[mt], b_l[nt]);
                    mma16816(acc[mt][nt], a_l[mt], b_h[nt]);
                }
        }
        __syncthreads();
    }

    // epilogue (vectorized: 2 consecutive n per store)
    bool do_bias = (mode & 4) && (blockIdx.z == 0);
    #pragma unroll
    for (int mt = 0; mt < 4; mt++) {
        #pragma unroll
        for (int nt = 0; nt < 4; nt++) {
            int n = n0 + wn*32 + nt*8 + tq*2;
            if (n >= N) continue;
            float b0 = 0.f, b1 = 0.f;
            if (do_bias) { b0 = bias[n]; b1 = bias[n+1]; }
            #pragma unroll
            for (int half = 0; half < 2; half++) {
                int m = m0 + wm*64 + mt*16 + tg + half*8;
                float v0 = acc[mt][nt][half*2]     + b0;
                float v1 = acc[mt][nt][half*2 + 1] + b1;
                if (mode & 8) { v0 = fmaxf(v0, 0.f); v1 = fmaxf(v1, 0.f); }
                if (skipmode == 2) {
                    int j = n - 1023 + m;       // pre-shifted column
                    float* row = Cf + offC + (ll)m * ldc;
                    if (j >= 0)     row[j]     = v0;
                    if (j + 1 >= 0) row[j + 1] = v1;
                    continue;
                }
                ll cidx = offC + (ll)m * ldc + n;
                if (mode & 1) *(float2*)(Cf + cidx) = make_float2(v0, v1);
                if (mode & 2) {
                    uint32_t hi, lo;
                    pack_split(v0, v1, hi, lo);
                    *(uint32_t*)(Chi + cidx) = hi;
                    *(uint32_t*)(Clo + cidx) = lo;
                }
            }
        }
    }
}

// ================= fused flash attention (Q in registers; 2 CTAs/SM) =================
__device__ __forceinline__ void flash_load_kv(uint32_t base,
        const bf16* __restrict__ Kh, const bf16* __restrict__ Kl,
        const bf16* __restrict__ Vh, const bf16* __restrict__ Vl,
        int j0, int tid)
{
    #pragma unroll
    for (int c = tid; c < 2048; c += 256) {
        int t4 = c >> 9;           // 0 Kh, 1 Kl, 2 Vh, 3 Vl
        int r  = (c >> 3) & 63;
        int qq = c & 7;
        uint32_t dst = base + t4*9216 + r*144 + qq*16;
        const bf16* src;
        if (t4 == 0)      src = Kh + (ll)(j0 + r)*6144 + qq*8;
        else if (t4 == 1) src = Kl + (ll)(j0 + r)*6144 + qq*8;
        else if (t4 == 2) src = Vh + (ll)r*2048 + j0 + qq*8;
        else              src = Vl + (ll)r*2048 + j0 + qq*8;
        cpasync16(dst, src, 16);
    }
    cp_commit();
}

__global__ void __launch_bounds__(256, 2)
k_flash(const bf16* __restrict__ qh_, const bf16* __restrict__ ql_,
        const bf16* __restrict__ kh_, const bf16* __restrict__ kl_,
        const bf16* __restrict__ vh_, const bf16* __restrict__ vl_,
        const float* __restrict__ bd_,
        bf16* __restrict__ voh, bf16* __restrict__ vol)
{
    extern __shared__ char sm[];
    const int STSZ = 36864;        // per-stage KV buffer; 2 stages total = 73728

    int tid = threadIdx.x, wid = tid >> 5, lane = tid & 31;
    int tg = lane >> 2, tq = lane & 3;
    int i0 = (7 - (int)blockIdx.x) << 7;   // heavy causal blocks scheduled first
    int z  = blockIdx.y;
    int b = z >> 3, h_ = z & 7;
    uint32_t sb = smem_u32(sm);

    const bf16* Qh = qh_ + (ll)z*65536 + (ll)i0*64;
    const bf16* Ql = ql_ + (ll)z*65536 + (ll)i0*64;
    const bf16* Kh = kh_ + (ll)b*1536 + h_*64;
    const bf16* Kl = kl_ + (ll)b*1536 + h_*64;
    const bf16* Vh = vh_ + (ll)z*131072;
    const bf16* Vl = vl_ + (ll)z*131072;
    const float* BD = bd_ + (ll)z*2097152;

    // ---- stage Q into stage-0 buffer, extract per-warp fragments, then reuse ----
    #pragma unroll
    for (int c = tid; c < 2048; c += 256) {
        int part = c >> 10, r = (c >> 3) & 127, qq = c & 7;
        cpasync16(sb + part*18432 + r*144 + qq*16,
                  (part ? Ql : Qh) + (ll)r*64 + qq*8, 16);
    }
    cp_commit();
    cp_wait0();
    __syncthreads();

    uint32_t qfh[4][4], qfl[4][4];
    {
        const uint32_t* Qsh = (const uint32_t*)(sm);
        const uint32_t* Qsl = (const uint32_t*)(sm + 18432);
        int r0 = (wid*16 + tg) * 36, r1 = r0 + 8*36;
        #pragma unroll
        for (int kt = 0; kt < 4; kt++) {
            int kw = kt*8 + tq;
            qfh[kt][0]=Qsh[r0+kw]; qfh[kt][1]=Qsh[r1+kw]; qfh[kt][2]=Qsh[r0+kw+4]; qfh[kt][3]=Qsh[r1+kw+4];
            qfl[kt][0]=Qsl[r0+kw]; qfl[kt][1]=Qsl[r1+kw]; qfl[kt][2]=Qsl[r0+kw+4]; qfl[kt][3]=Qsl[r1+kw+4];
        }
    }
    __syncthreads();   // all warps done reading Q before stage-0 becomes KV

    int jbmax = ((i0 + 127 + MLEN) >> 6) + 1;
    if (jbmax > 32) jbmax = 32;
    flash_load_kv(sb, Kh, Kl, Vh, Vl, 0, tid);

    float O[8][4];
    #pragma unroll
    for (int dt = 0; dt < 8; dt++) { O[dt][0]=O[dt][1]=O[dt][2]=O[dt][3]=0.f; }
    float mA = -1e30f, mB = -1e30f, lA = 0.f, lB = 0.f;
    int riA = i0 + wid*16 + tg, riB = riA + 8;

    const float* BDrA = BD + (ll)riA*2048;
    const float* BDrB = BD + (ll)riB*2048;

    for (int jb = 0; jb < jbmax; jb++) {
        int s = jb & 1;
        if (jb + 1 < jbmax) {
            flash_load_kv(sb + (s^1)*STSZ, Kh, Kl, Vh, Vl, (jb+1) << 6, tid);
            cp_wait1();
        } else {
            cp_wait0();
        }
        __syncthreads();

        const uint32_t* Ksh = (const uint32_t*)(sm + s*STSZ);
        const uint32_t* Ksl = Ksh + 2304;
        const uint32_t* Vsh = Ksh + 4608;
        const uint32_t* Vsl = Ksh + 6912;
        int j0 = jb << 6;

        float S[8][4];
        #pragma unroll
        for (int nt = 0; nt < 8; nt++) { S[nt][0]=S[nt][1]=S[nt][2]=S[nt][3]=0.f; }

        #pragma unroll
        for (int kt = 0; kt < 4; kt++) {
            int kw = kt*8 + tq;
            #pragma unroll
            for (int nt = 0; nt < 8; nt++) {
                int nr = (nt*8 + tg) * 36;
                uint32_t bh2[2], bl2[2];
                bh2[0]=Ksh[nr+kw]; bh2[1]=Ksh[nr+kw+4];
                bl2[0]=Ksl[nr+kw]; bl2[1]=Ksl[nr+kw+4];
                mma16816(S[nt], qfh[kt], bh2);
                mma16816(S[nt], qfh[kt], bl2);
                mma16816(S[nt], qfl[kt], bh2);
            }
        }

        float bmA = -1e30f, bmB = -1e30f;
        #pragma unroll
        for (int nt = 0; nt < 8; nt++) {
            int j = j0 + nt*8 + 2*tq;
            float2 bA = *(const float2*)(BDrA + j);
            float2 bB = *(const float2*)(BDrB + j);
            S[nt][0] = (j     <= riA + MLEN) ? (S[nt][0] + bA.x)*0.125f : -1e30f;
            S[nt][1] = (j + 1 <= riA + MLEN) ? (S[nt][1] + bA.y)*0.125f : -1e30f;
            S[nt][2] = (j     <= riB + MLEN) ? (S[nt][2] + bB.x)*0.125f : -1e30f;
            S[nt][3] = (j + 1 <= riB + MLEN) ? (S[nt][3] + bB.y)*0.125f : -1e30f;
            bmA = fmaxf(bmA, fmaxf(S[nt][0], S[nt][1]));
            bmB = fmaxf(bmB, fmaxf(S[nt][2], S[nt][3]));
        }
        bmA = fmaxf(bmA, __shfl_xor_sync(0xffffffffu, bmA, 1));
        bmA = fmaxf(bmA, __shfl_xor_sync(0xffffffffu, bmA, 2));
        bmB = fmaxf(bmB, __shfl_xor_sync(0xffffffffu, bmB, 1));
        bmB = fmaxf(bmB, __shfl_xor_sync(0xffffffffu, bmB, 2));
        float mAn = fmaxf(mA, bmA), mBn = fmaxf(mB, bmB);
        float aAs = __expf(mA - mAn), aBs = __expf(mB - mBn);

        float sA = 0.f, sB = 0.f;
        #pragma unroll
        for (int nt = 0; nt < 8; nt++) {
            S[nt][0] = __expf(S[nt][0] - mAn);
            S[nt][1] = __expf(S[nt][1] - mAn);
            S[nt][2] = __expf(S[nt][2] - mBn);
            S[nt][3] = __expf(S[nt][3] - mBn);
            sA += S[nt][0] + S[nt][1];
            sB += S[nt][2] + S[nt][3];
            O[nt][0] *= aAs; O[nt][1] *= aAs; O[nt][2] *= aBs; O[nt][3] *= aBs;
        }
        sA += __shfl_xor_sync(0xffffffffu, sA, 1);
        sA += __shfl_xor_sync(0xffffffffu, sA, 2);
        sB += __shfl_xor_sync(0xffffffffu, sB, 1);
        sB += __shfl_xor_sync(0xffffffffu, sB, 2);
        lA = lA*aAs + sA; lB = lB*aBs + sB;
        mA = mAn; mB = mBn;

        #pragma unroll
        for (int kt = 0; kt < 4; kt++) {
            uint32_t pah[4], pal[4];
            pack_split(S[2*kt][0],   S[2*kt][1],   pah[0], pal[0]);
            pack_split(S[2*kt][2],   S[2*kt][3],   pah[1], pal[1]);
            pack_split(S[2*kt+1][0], S[2*kt+1][1], pah[2], pal[2]);
            pack_split(S[2*kt+1][2], S[2*kt+1][3], pah[3], pal[3]);
            int kw = kt*8 + tq;
            #pragma unroll
            for (int dt = 0; dt < 8; dt++) {
                int nr = (dt*8 + tg) * 36;
                uint32_t bh2[2], bl2[2];
                bh2[0]=Vsh[nr+kw]; bh2[1]=Vsh[nr+kw+4];
                bl2[0]=Vsl[nr+kw]; bl2[1]=Vsl[nr+kw+4];
                mma16816(O[dt], pah, bh2);
                mma16816(O[dt], pah, bl2);
                mma16816(O[dt], pal, bh2);
            }
        }
        __syncthreads();
    }

    float ivA = 1.f/lA, ivB = 1.f/lB;
    #pragma unroll
    for (int dt = 0; dt < 8; dt++) {
        int d0 = dt*8 + 2*tq;
        ll aA = (ll)riA*2048 + b*512 + h_*64 + d0;
        ll aB = (ll)riB*2048 + b*512 + h_*64 + d0;
        uint32_t hi, lo;
        pack_split(O[dt][0]*ivA, O[dt][1]*ivA, hi, lo);
        *(uint32_t*)(voh + aA) = hi; *(uint32_t*)(vol + aA) = lo;
        pack_split(O[dt][2]*ivB, O[dt][3]*ivB, hi, lo);
        *(uint32_t*)(voh + aB) = hi; *(uint32_t*)(vol + aB) = lo;
    }
}

// ================= elementwise / small kernels =================
__global__ void k_split(const float4* __restrict__ in, uint2* __restrict__ hi,
                        uint2* __restrict__ lo, ll n4){
    ll i = (ll)blockIdx.x * blockDim.x + threadIdx.x;
    if (i >= n4) return;
    float4 v = in[i];
    uint32_t h0,l0,h1,l1;
    pack_split(v.x, v.y, h0, l0);
    pack_split(v.z, v.w, h1, l1);
    hi[i] = make_uint2(h0, h1);
    lo[i] = make_uint2(l0, l1);
}

__global__ void k_embed(const int* __restrict__ x, const float* __restrict__ emb,
                        float* __restrict__ h, bf16* __restrict__ hh, bf16* __restrict__ hl)
{
    int idx = blockIdx.x * blockDim.x + threadIdx.x;
    if (idx >= QLEN*BSZ*DM) return;
    int d = idx & (DM-1);
    int b = (idx >> 9) & 3;
    int i = idx >> 11;
    int tok = x[i*BSZ + b];
    float v = emb[(ll)tok*DM + d] * 22.627416997969522f;
    h[idx] = v;
    split2(v, hh + idx, hl + idx);
}

__global__ void k_posemb(bf16* __restrict__ rh, bf16* __restrict__ rl)
{
    int idx = blockIdx.x * blockDim.x + threadIdx.x;
    if (idx >= KLEN*DM) return;
    int d = idx & (DM-1);
    int k = idx >> 9;
    double pos = (double)(KLEN - 1 - k);
    int t = (d < 256) ? d : d - 256;
    double f = exp(-(double)t * (log(10000.0) / 256.0));
    double a = pos * f;
    float v = (float)((d < 256) ? sin(a) : cos(a));
    split2(v, rh + idx, rl + idx);
}

// q + biases, re-split into [bh][i][64]
__global__ void k_qbias(const bf16* __restrict__ hh, const bf16* __restrict__ hl,
                        const float* __restrict__ rwb, const float* __restrict__ rrb,
                        bf16* __restrict__ qwh, bf16* __restrict__ qwl,
                        bf16* __restrict__ qrh, bf16* __restrict__ qrl)
{
    int idx = blockIdx.x * blockDim.x + threadIdx.x;
    if (idx >= 32*1024*64) return;
    int d = idx & 63;
    int i = (idx >> 6) & 1023;
    int z = idx >> 16;
    int b = z >> 3, h_ = z & 7;
    ll src = ((ll)(MLEN + i)*BSZ + b)*QKV + h_*64 + d;
    float q = __bfloat162float(hh[src]) + __bfloat162float(hl[src]);
    split2(q + rwb[h_*64 + d], qwh + idx, qwl + idx);
    split2(q + rrb[h_*64 + d], qrh + idx, qrl + idx);
}

__global__ void k_vtrans(const bf16* __restrict__ hh, const bf16* __restrict__ hl,
                         bf16* __restrict__ vth, bf16* __restrict__ vtl)
{
    __shared__ bf16 th[64][65], tl[64][65];
    int z = blockIdx.y;
    int j0 = blockIdx.x << 6;
    int b = z >> 3, h_ = z & 7;
    #pragma unroll
    for (int p = 0; p < 16; p++) {
        int jj = (threadIdx.x >> 6) + p*4;
        int d  = threadIdx.x & 63;
        ll src = ((ll)(j0 + jj)*BSZ + b)*QKV + 1024 + h_*64 + d;
        th[jj][d] = hh[src];
        tl[jj][d] = hl[src];
    }
    __syncthreads();
    #pragma unroll
    for (int p = 0; p < 16; p++) {
        int dd = (threadIdx.x >> 6) + p*4;
        int j  = threadIdx.x & 63;
        ll dst = (ll)z*131072 + (ll)dd*2048 + j0 + j;
        vth[dst] = th[j][dd];
        vtl[dst] = tl[j][dd];
    }
}

// h = LN(h + res + res2)  — two split-K partial residuals
__global__ void __launch_bounds__(256)
k_add_ln(float* __restrict__ h, const float* __restrict__ res, const float* __restrict__ res2,
         const float* __restrict__ g, const float* __restrict__ be,
         bf16* __restrict__ hh, bf16* __restrict__ hl)
{
    int row = blockIdx.x;
    int tid = threadIdx.x;
    int lane = tid & 31, wid = tid >> 5;
    __shared__ float red[8];
    __shared__ float s_mean, s_rstd;

    float* hp = h + (ll)row*DM;
    const float* rp  = res  + (ll)row*DM;
    const float* rp2 = res2 + (ll)row*DM;

    float v0 = hp[tid]       + rp[tid]       + rp2[tid];
    float v1 = hp[tid + 256] + rp[tid + 256] + rp2[tid + 256];

    float s = v0 + v1;
    #pragma unroll
    for (int o = 16; o > 0; o >>= 1) s += __shfl_xor_sync(0xffffffffu, s, o);
    if (lane == 0) red[wid] = s;
    __syncthreads();
    if (wid == 0) {
        float t = (lane < 8) ? red[lane] : 0.f;
        #pragma unroll
        for (int o = 4; o > 0; o >>= 1) t += __shfl_xor_sync(0xffffffffu, t, o);
        if (lane == 0) s_mean = t * (1.0f/512.0f);
    }
    __syncthreads();
    float mean = s_mean;
    float d0 = v0 - mean, d1 = v1 - mean;

    s = d0*d0 + d1*d1;
    #pragma unroll
    for (int o = 16; o > 0; o >>= 1) s += __shfl_xor_sync(0xffffffffu, s, o);
    if (lane == 0) red[wid] = s;
    __syncthreads();
    if (wid == 0) {
        float t = (lane < 8) ? red[lane] : 0.f;
        #pragma unroll
        for (int o = 4; o > 0; o >>= 1) t += __shfl_xor_sync(0xffffffffu, t, o);
        if (lane == 0) s_rstd = rsqrtf(t * (1.0f/512.0f) + 1e-5f);
    }
    __syncthreads();
    float rs = s_rstd;

    float o0 = d0 * rs * g[tid]       + be[tid];
    float o1 = d1 * rs * g[tid + 256] + be[tid + 256];
    hp[tid]       = o0;
    hp[tid + 256] = o1;
    ll base = (ll)row*DM;
    split2(o0, hh + base + tid,       hl + base + tid);
    split2(o1, hh + base + tid + 256, hl + base + tid + 256);
}

// ================= host =================
static const int SMGEMM = 2*4*128*80;      // 81920
static const int SMFLSH = 2*36864;         // 73728 -> 2 CTAs/SM

extern "C" void kernel_launch(void* const* d_in, const int* in_sizes, int n_in,
                              void* d_out, int out_size)
{
    const int*   x        = (const int*)  d_in[0];
    const float* mems     = (const float*)d_in[1];
    const float* emb      = (const float*)d_in[2];
    const float* qkv_w    = (const float*)d_in[3];
    const float* r_net_w  = (const float*)d_in[4];
    const float* o_w      = (const float*)d_in[5];
    const float* ln1_g    = (const float*)d_in[6];
    const float* ln1_b    = (const float*)d_in[7];
    const float* ff_w1    = (const float*)d_in[8];
    const float* ff_b1    = (const float*)d_in[9];
    const float* ff_w2    = (const float*)d_in[10];
    const float* ff_b2    = (const float*)d_in[11];
    const float* ln2_g    = (const float*)d_in[12];
    const float* ln2_b    = (const float*)d_in[13];
    const float* r_w_bias = (const float*)d_in[14];
    const float* r_r_bias = (const float*)d_in[15];
    const float* proj_w   = (const float*)d_in[16];
    const float* proj_b   = (const float*)d_in[17];
    float* out = (float*)d_out;

    static bool attr_done = false;
    if (!attr_done) {
        cudaFuncSetAttribute(k_gemm,  cudaFuncAttributeMaxDynamicSharedMemorySize, SMGEMM);
        cudaFuncSetAttribute(k_flash, cudaFuncAttributeMaxDynamicSharedMemorySize, SMFLSH);
        attr_done = true;
    }

    bf16 *qkvwh,*qkvwl,*rnwh,*rnwl,*owh,*owl,*f1h,*f1l,*f2h,*f2l,*pwh,*pwl,*memh,*meml;
    bf16 *hdh,*hdl,*rh,*rl,*rkh,*rkl,*qwh,*qwl,*qrh,*qrl;
    bf16 *vth,*vtl,*vech,*vecl,*hh,*hl,*ffh,*ffl;
    float *bd,*h,*tmp;
    cudaGetSymbolAddress((void**)&qkvwh, g_qkvwh); cudaGetSymbolAddress((void**)&qkvwl, g_qkvwl);
    cudaGetSymbolAddress((void**)&rnwh,  g_rnwh);  cudaGetSymbolAddress((void**)&rnwl,  g_rnwl);
    cudaGetSymbolAddress((void**)&owh,   g_owh);   cudaGetSymbolAddress((void**)&owl,   g_owl);
    cudaGetSymbolAddress((void**)&f1h,   g_f1h);   cudaGetSymbolAddress((void**)&f1l,   g_f1l);
    cudaGetSymbolAddress((void**)&f2h,   g_f2h);   cudaGetSymbolAddress((void**)&f2l,   g_f2l);
    cudaGetSymbolAddress((void**)&pwh,   g_pwh);   cudaGetSymbolAddress((void**)&pwl,   g_pwl);
    cudaGetSymbolAddress((void**)&memh,  g_memh);  cudaGetSymbolAddress((void**)&meml,  g_meml);
    cudaGetSymbolAddress((void**)&hdh,   g_hdh);   cudaGetSymbolAddress((void**)&hdl,   g_hdl);
    cudaGetSymbolAddress((void**)&rh,    g_rh);    cudaGetSymbolAddress((void**)&rl,    g_rl);
    cudaGetSymbolAddress((void**)&rkh,   g_rkh);   cudaGetSymbolAddress((void**)&rkl,   g_rkl);
    cudaGetSymbolAddress((void**)&qwh,   g_qwh);   cudaGetSymbolAddress((void**)&qwl,   g_qwl);
    cudaGetSymbolAddress((void**)&qrh,   g_qrh);   cudaGetSymbolAddress((void**)&qrl,   g_qrl);
    cudaGetSymbolAddress((void**)&vth,   g_vth);   cudaGetSymbolAddress((void**)&vtl,   g_vtl);
    cudaGetSymbolAddress((void**)&vech,  g_vech);  cudaGetSymbolAddress((void**)&vecl,  g_vecl);
    cudaGetSymbolAddress((void**)&hh,    g_hh);    cudaGetSymbolAddress((void**)&hl,    g_hl);
    cudaGetSymbolAddress((void**)&ffh,   g_ffh);   cudaGetSymbolAddress((void**)&ffl,   g_ffl);
    cudaGetSymbolAddress((void**)&bd,    g_bd);
    cudaGetSymbolAddress((void**)&h,     g_h);     cudaGetSymbolAddress((void**)&tmp,   g_tmp);
    float* tmp2 = tmp + 2097152;

    const int NTOK = QLEN*BSZ;

    k_split<<<(2359296 +255)/256, 256>>>((const float4*)qkv_w, (uint2*)qkvwh, (uint2*)qkvwl, 2359296LL);
    k_embed <<<(QLEN*BSZ*DM + 255)/256, 256>>>(x, emb, h, hh, hl);
    k_split<<<(6291456 +255)/256, 256>>>((const float4*)mems, (uint2*)memh, (uint2*)meml, 6291456LL);

    // #4 (ncu capture slot): layer-0 QKV GEMM
    k_gemm<<<dim3(12, 64, 1), 256, SMGEMM>>>(
        memh, meml, hh, hl, 4096,
        512, 0, 0,
        qkvwh, qkvwl, 512, 0, 0,
        nullptr, hdh, hdl, 1536, 0, 0,
        nullptr, 1536, 512, 1, 2, 4);

    k_posemb<<<(KLEN*DM + 255)/256, 256>>>(rh, rl);
    k_split<<<(786432  +255)/256, 256>>>((const float4*)r_net_w, (uint2*)rnwh, (uint2*)rnwl, 786432LL);

    // ALL-layer rhk in ONE batched GEMM: rk[l] = r x r_net_w[l]^T  (z = layer)
    k_gemm<<<dim3(4, 16, 12), 256, SMGEMM>>>(
        rh, rl, nullptr, nullptr, 0,
        512, 0, 0,
        rnwh, rnwl, 512, 262144, 0,
        nullptr, rkh, rkl, 512, 1048576, 0,
        nullptr, 512, 512, 1, 2, 0);

    k_split<<<(786432  +255)/256, 256>>>((const float4*)o_w,    (uint2*)owh, (uint2*)owl, 786432LL);
    k_split<<<(3145728 +255)/256, 256>>>((const float4*)ff_w1,  (uint2*)f1h, (uint2*)f1l, 3145728LL);
    k_split<<<(3145728 +255)/256, 256>>>((const float4*)ff_w2,  (uint2*)f2h, (uint2*)f2l, 3145728LL);
    k_split<<<(1280000 +255)/256, 256>>>((const float4*)proj_w, (uint2*)pwh, (uint2*)pwl, 1280000LL);

    for (int l = 0; l < NL; l++) {
        if (l > 0) {
            k_gemm<<<dim3(12, 64, 1), 256, SMGEMM>>>(
                memh + (ll)l*2097152, meml + (ll)l*2097152, hh, hl, 4096,
                512, 0, 0,
                qkvwh + (ll)l*786432, qkvwl + (ll)l*786432, 512, 0, 0,
                nullptr, hdh, hdl, 1536, 0, 0,
                nullptr, 1536, 512, 1, 2, 4);
        }

        // q + biases
        k_qbias<<<(32*1024*64 + 255)/256, 256>>>(hdh, hdl, r_w_bias, r_r_bias, qwh, qwl, qrh, qrl);

        // BD raw -> PRE-SHIFTED store (skipmode 2); rhk from batched buffer
        k_gemm<<<dim3(16, 8, 32), 256, SMGEMM>>>(
            qrh, qrl, nullptr, nullptr, 0,
            64, 8LL*65536, 65536,
            rkh + (ll)l*1048576, rkl + (ll)l*1048576, 512, 0, 64,
            bd, nullptr, nullptr, 2048, 8LL*2097152, 2097152,
            nullptr, 2048, 64, 8, 1, 2);

        // V transpose
        k_vtrans<<<dim3(32, 32), 256>>>(hdh, hdl, vth, vtl);

        // fused AC + BDshift + mask + softmax + PV (Q-in-regs, 2 CTAs/SM)
        k_flash<<<dim3(8, 32), 256, SMFLSH>>>(
            qwh, qwl, hdh + 512, hdl + 512, vth, vtl, bd, vech, vecl);

        // attn_out = vec x o_w^T  — SPLIT-K x2
        k_gemm<<<dim3(4, 32, 2), 256, SMGEMM>>>(
            vech, vecl, nullptr, nullptr, 0,
            512, 256, 0,
            owh + (ll)l*262144, owl + (ll)l*262144, 512, 256, 0,
            tmp, nullptr, nullptr, 512, 2097152, 0,
            nullptr, 512, 256, 1, 1, 0);

        k_add_ln<<<NTOK, 256>>>(h, tmp, tmp2, ln1_g + l*DM, ln1_b + l*DM, hh, hl);

        // ff = relu(h x ff_w1^T + b1)
        k_gemm<<<dim3(16, 32, 1), 256, SMGEMM>>>(
            hh, hl, nullptr, nullptr, 0,
            512, 0, 0,
            f1h + (ll)l*1048576, f1l + (ll)l*1048576, 512, 0, 0,
            nullptr, ffh, ffl, 2048, 0, 0,
            ff_b1 + (ll)l*DI, 2048, 512, 1, 2|4|8, 0);

        // tmp = ff x ff_w2^T + b2  — SPLIT-K x2 (bias by z=0 only)
        k_gemm<<<dim3(4, 32, 2), 256, SMGEMM>>>(
            ffh, ffl, nullptr, nullptr, 0,
            2048, 1024, 0,
            f2h + (ll)l*1048576, f2l + (ll)l*1048576, 2048, 1024, 0,
            tmp, nullptr, nullptr, 512, 2097152, 0,
            ff_b2 + (ll)l*DM, 512, 1024, 1, 1|4, 0);

        k_add_ln<<<NTOK, 256>>>(h, tmp, tmp2, ln2_g + l*DM, ln2_b + l*DM, hh, hl);
    }

    // logits = h x proj_w^T + proj_b
    k_gemm<<<dim3(79, 32, 1), 256, SMGEMM>>>(
        hh, hl, nullptr, nullptr, 0,
        512, 0, 0,
        pwh, pwl, 512, 0, 0,
        out, nullptr, nullptr, 10000, 0, 0,
        proj_b, 10000, 512, 1, 1|4, 0);
}